// round 11
// baseline (speedup 1.0000x reference)
#include <cuda_runtime.h>
#include <cuda_fp16.h>
#include <math.h>
#include <stdint.h>
#include <stddef.h>

// Problem constants
#define BATCH 4
#define SEQ   2048
#define EMB   1024
#define HEADS 16
#define HDIM  64
#define M_ROWS (BATCH*SEQ)   // 8192

// Scratch (device globals — allocation-free per harness rules)
__device__ __half g_xh[(size_t)M_ROWS * EMB];        // x f16
__device__ __half g_wqkvh[(size_t)EMB * 3 * EMB];    // W_qkv f16 [K,N]
__device__ __half g_woh[(size_t)EMB * EMB];          // W_o f16 [K,N]
__device__ __half g_qkvh[(size_t)M_ROWS * 3 * EMB];  // qkv f16
__device__ __half g_attnh[(size_t)M_ROWS * EMB];     // attention out f16

// ---------------------------------------------------------------------------
// Helpers
// ---------------------------------------------------------------------------
__device__ __forceinline__ uint32_t ph2(float a, float b) {
    __half2 h = __floats2half2_rn(a, b);
    return *reinterpret_cast<uint32_t*>(&h);
}
__device__ __forceinline__ uint32_t s2u(const void* p) {
    uint32_t r;
    asm("{ .reg .u64 t; cvta.to.shared.u64 t, %1; cvt.u32.u64 %0, t; }"
        : "=r"(r) : "l"(p));
    return r;
}

#define MMA_F16(d0,d1,d2,d3, a0,a1,a2,a3, b0,b1)                            \
    asm volatile(                                                           \
        "mma.sync.aligned.m16n8k16.row.col.f32.f16.f16.f32 "                \
        "{%0,%1,%2,%3}, {%4,%5,%6,%7}, {%8,%9}, {%0,%1,%2,%3};"             \
        : "+f"(d0), "+f"(d1), "+f"(d2), "+f"(d3)                            \
        : "r"(a0), "r"(a1), "r"(a2), "r"(a3), "r"(b0), "r"(b1))

__device__ __forceinline__ void ldsm_x4(uint32_t& r0, uint32_t& r1,
                                        uint32_t& r2, uint32_t& r3, uint32_t addr) {
    asm volatile("ldmatrix.sync.aligned.m8n8.x4.shared.b16 {%0,%1,%2,%3}, [%4];"
                 : "=r"(r0), "=r"(r1), "=r"(r2), "=r"(r3) : "r"(addr));
}
__device__ __forceinline__ void ldsm_x4t(uint32_t& r0, uint32_t& r1,
                                         uint32_t& r2, uint32_t& r3, uint32_t addr) {
    asm volatile("ldmatrix.sync.aligned.m8n8.x4.trans.shared.b16 {%0,%1,%2,%3}, [%4];"
                 : "=r"(r0), "=r"(r1), "=r"(r2), "=r"(r3) : "r"(addr));
}
__device__ __forceinline__ void cp16(uint32_t dst, const void* src) {
    asm volatile("cp.async.cg.shared.global [%0], [%1], 16;"
                 :: "r"(dst), "l"(src) : "memory");
}
#define CP_COMMIT() asm volatile("cp.async.commit_group;" ::: "memory")
#define CP_WAIT(n)  asm volatile("cp.async.wait_group %0;" :: "n"(n) : "memory")

// ---------------------------------------------------------------------------
// Pre-pass: f32 -> f16
// ---------------------------------------------------------------------------
__global__ __launch_bounds__(256)
void f32_to_f16(const float* __restrict__ in, __half* __restrict__ out, int n4) {
    int i = blockIdx.x * 256 + threadIdx.x;
    if (i < n4) {
        float4 v = reinterpret_cast<const float4*>(in)[i];
        uint2 o = make_uint2(ph2(v.x, v.y), ph2(v.z, v.w));
        reinterpret_cast<uint2*>(out)[i] = o;
    }
}

// ---------------------------------------------------------------------------
// f16 tensor-core GEMM: C[M,N] = A[M,K] @ B[K,N] + bias
// CTA 256x128x64, 512 threads / 16 warps (4x4), warp tile 64x32.
// 2-stage cp.async, ONE __syncthreads per chunk (loads issued post-sync
// into the opposite stage — no WAR hazard, no trailing barrier).
// ---------------------------------------------------------------------------
#define GBM 256
#define GBN 128
#define GBK 64
#define APAD_B 144                  // bytes per A row (128 data + 16 pad)
#define BPAD_B 272                  // bytes per B row (256 data + 16 pad)
#define ASTG_B (GBM * APAD_B)       // 36864 B
#define BSTG_B (GBK * BPAD_B)       // 17408 B
#define GSMEM (2 * (ASTG_B + BSTG_B))   // 108544 B

template <typename OutT>
__global__ __launch_bounds__(512, 1)
void gemm_f16(const __half* __restrict__ A, const __half* __restrict__ B,
              const float* __restrict__ bias, OutT* __restrict__ C,
              int M, int N, int K)
{
    extern __shared__ __align__(16) char smem[];
    const int tid  = threadIdx.x;
    const int wid  = tid >> 5;
    const int lane = tid & 31;
    const int g = lane >> 2;
    const int t = lane & 3;
    const int wm = (wid >> 2) * 64;   // 0/64/128/192
    const int wn = (wid & 3) * 32;    // 0/32/64/96
    const int n0 = blockIdx.x * GBN;
    const int m0 = blockIdx.y * GBM;

    const uint32_t smA_u = s2u(smem);
    const uint32_t smB_u = smA_u + 2 * ASTG_B;

    const __half* Ab = A + (size_t)m0 * K;
    const __half* Bb = B + n0;

    float acc[4][4][4];
    #pragma unroll
    for (int i = 0; i < 4; ++i)
        #pragma unroll
        for (int j = 0; j < 4; ++j)
            #pragma unroll
            for (int c = 0; c < 4; ++c) acc[i][j][c] = 0.f;

    const int ntiles = K / GBK;

    // A chunk: 256 rows x 128 B = 2048 cp16 -> 4/thread.
    // B chunk: 64 rows x 256 B  = 1024 cp16 -> 2/thread.
    #define LOAD_CHUNK(kc, st) do {                                              \
        const int _k0 = (kc) * GBK;                                              \
        const uint32_t _aB = smA_u + (st) * ASTG_B;                              \
        const uint32_t _bB = smB_u + (st) * BSTG_B;                              \
        _Pragma("unroll")                                                        \
        for (int _i = 0; _i < 4; ++_i) {                                         \
            int _idx = tid + _i * 512;                                           \
            int _ar = _idx >> 3, _ac = _idx & 7;                                 \
            cp16(_aB + _ar * APAD_B + _ac * 16,                                  \
                 Ab + (size_t)_ar * K + _k0 + _ac * 8);                          \
        }                                                                        \
        _Pragma("unroll")                                                        \
        for (int _i = 0; _i < 2; ++_i) {                                         \
            int _idx = tid + _i * 512;                                           \
            int _br = _idx >> 4, _bc = _idx & 15;                                \
            cp16(_bB + _br * BPAD_B + _bc * 16,                                  \
                 Bb + (size_t)(_k0 + _br) * N + _bc * 8);                        \
        }                                                                        \
        CP_COMMIT();                                                             \
    } while (0)

    // prologue: chunk 0 -> stage 0
    LOAD_CHUNK(0, 0);

    for (int kt = 0; kt < ntiles; ++kt) {
        const int s = kt & 1;
        CP_WAIT(0);          // chunk kt landed (only group in flight)
        __syncthreads();     // all warps done reading stage s^1 (iter kt-1)
        if (kt + 1 < ntiles)
            LOAD_CHUNK(kt + 1, s ^ 1);   // overlaps with compute below

        const uint32_t aS = smA_u + s * ASTG_B;
        const uint32_t bS = smB_u + s * BSTG_B;

        #pragma unroll
        for (int ks = 0; ks < 4; ++ks) {      // 4 x k16 per chunk
            uint32_t a[4][4], bfr[4][2];
            #pragma unroll
            for (int mf = 0; mf < 4; ++mf) {
                uint32_t addr = aS
                    + (uint32_t)(wm + mf * 16 + (lane & 15)) * APAD_B
                    + (uint32_t)(ks * 16 + ((lane >> 4) << 3)) * 2;
                ldsm_x4(a[mf][0], a[mf][1], a[mf][2], a[mf][3], addr);
            }
            #pragma unroll
            for (int p = 0; p < 2; ++p) {     // nf pairs (0,1) and (2,3)
                uint32_t addr = bS
                    + (uint32_t)(ks * 16 + (lane & 15)) * BPAD_B
                    + (uint32_t)(wn + p * 16 + ((lane >> 4) << 3)) * 2;
                ldsm_x4t(bfr[2 * p][0], bfr[2 * p][1],
                         bfr[2 * p + 1][0], bfr[2 * p + 1][1], addr);
            }
            #pragma unroll
            for (int mf = 0; mf < 4; ++mf)
                #pragma unroll
                for (int nf = 0; nf < 4; ++nf)
                    MMA_F16(acc[mf][nf][0], acc[mf][nf][1],
                            acc[mf][nf][2], acc[mf][nf][3],
                            a[mf][0], a[mf][1], a[mf][2], a[mf][3],
                            bfr[nf][0], bfr[nf][1]);
        }
    }
    #undef LOAD_CHUNK

    // epilogue
    #pragma unroll
    for (int mf = 0; mf < 4; ++mf) {
        const int row = m0 + wm + mf * 16 + g;
        #pragma unroll
        for (int nf = 0; nf < 4; ++nf) {
            const int col = n0 + wn + nf * 8 + 2 * t;
            float2 b2 = *reinterpret_cast<const float2*>(bias + col);
            float o00 = acc[mf][nf][0] + b2.x, o01 = acc[mf][nf][1] + b2.y;
            float o10 = acc[mf][nf][2] + b2.x, o11 = acc[mf][nf][3] + b2.y;
            if (sizeof(OutT) == 2) {
                __half* p0 = (__half*)C + (size_t)row * N + col;
                __half* p1 = (__half*)C + (size_t)(row + 8) * N + col;
                *reinterpret_cast<uint32_t*>(p0) = ph2(o00, o01);
                *reinterpret_cast<uint32_t*>(p1) = ph2(o10, o11);
            } else {
                float* p0 = (float*)C + (size_t)row * N + col;
                float* p1 = (float*)C + (size_t)(row + 8) * N + col;
                *reinterpret_cast<float2*>(p0) = make_float2(o00, o01);
                *reinterpret_cast<float2*>(p1) = make_float2(o10, o11);
            }
        }
    }
}

// ---------------------------------------------------------------------------
// f16 causal flash attention; cp.async double-buffered K/V, x4 ldmatrix.
// CTA: 128 threads / 4 warps; 64-query tile; 64-key K/V tiles. (R10, unchanged)
// ---------------------------------------------------------------------------
#define KSTH 72                      // halves per row (64 + 8 pad) -> 144 B
#define KROW_B (KSTH * 2)            // 144
#define KTILE_B (64 * KROW_B)        // 9216 per matrix
#define ASTAGE_B (2 * KTILE_B)       // K + V per stage: 18432
#define ASMEM (2 * ASTAGE_B)         // 36864

__global__ __launch_bounds__(128)
void attn_f16(__half* __restrict__ out)
{
    extern __shared__ __align__(16) char asmem[];
    const int b  = blockIdx.z;
    const int h  = blockIdx.y;
    const int qt = blockIdx.x;
    const int tid  = threadIdx.x;
    const int w    = tid >> 5;
    const int lane = tid & 31;
    const int g = lane >> 2;
    const int t = lane & 3;
    const int q0 = qt * 64;

    const size_t row3E = (size_t)3 * EMB;
    const __half* basep = g_qkvh + (size_t)b * SEQ * row3E;
    const uint32_t smu = s2u(asmem);

    // Q fragments (f16x2, pre-scaled by 1/8 — exact in f16)
    uint32_t qa[4][4];
    {
        const __half2 sc = __half2half2(__float2half_rn(0.125f));
        const __half* q0p = basep + (size_t)(q0 + w * 16 + g) * row3E + h * HDIM;
        const __half* q8p = q0p + 8 * row3E;
        #pragma unroll
        for (int ks = 0; ks < 4; ++ks) {
            __half2 v0 = *reinterpret_cast<const __half2*>(q0p + ks * 16 + 2 * t);
            __half2 v1 = *reinterpret_cast<const __half2*>(q8p + ks * 16 + 2 * t);
            __half2 v2 = *reinterpret_cast<const __half2*>(q0p + ks * 16 + 8 + 2 * t);
            __half2 v3 = *reinterpret_cast<const __half2*>(q8p + ks * 16 + 8 + 2 * t);
            v0 = __hmul2(v0, sc); v1 = __hmul2(v1, sc);
            v2 = __hmul2(v2, sc); v3 = __hmul2(v3, sc);
            qa[ks][0] = *reinterpret_cast<uint32_t*>(&v0);
            qa[ks][1] = *reinterpret_cast<uint32_t*>(&v1);
            qa[ks][2] = *reinterpret_cast<uint32_t*>(&v2);
            qa[ks][3] = *reinterpret_cast<uint32_t*>(&v3);
        }
    }

    float m0 = -INFINITY, m1 = -INFINITY, l0 = 0.f, l1 = 0.f;
    float o[8][4];
    #pragma unroll
    for (int nf = 0; nf < 8; ++nf)
        #pragma unroll
        for (int c = 0; c < 4; ++c) o[nf][c] = 0.f;

    #define LOAD_TILE(kt_, st_) do {                                             \
        const int _k0 = (kt_) * 64;                                              \
        const uint32_t _kB = smu + (st_) * ASTAGE_B;                             \
        const uint32_t _vB = _kB + KTILE_B;                                      \
        _Pragma("unroll")                                                        \
        for (int _i = 0; _i < 4; ++_i) {                                         \
            int _idx = tid + _i * 128;                                           \
            int _r = _idx >> 3;                                                  \
            int _cb = (_idx & 7) << 4;                                           \
            const __half* _rp = basep + (size_t)(_k0 + _r) * row3E + h * HDIM;   \
            cp16(_kB + _r * KROW_B + _cb, (const char*)(_rp + EMB) + _cb);       \
            cp16(_vB + _r * KROW_B + _cb, (const char*)(_rp + 2 * EMB) + _cb);   \
        }                                                                        \
        CP_COMMIT();                                                             \
    } while (0)

    const int ntile = q0 / 64 + 1;
    LOAD_TILE(0, 0);

    const int kq_row = lane & 7;
    const int kq_sel = (lane >> 4) & 1;
    const int kq_col = (lane >> 3) & 1;
    const int v_row = lane & 15;
    const int v_sel = (lane >> 4) & 1;

    for (int kt = 0; kt < ntile; ++kt) {
        const int st = kt & 1;
        if (kt + 1 < ntile) { CP_WAIT(1); } else { CP_WAIT(0); }
        __syncthreads();
        if (kt + 1 < ntile) LOAD_TILE(kt + 1, st ^ 1);

        const uint32_t kB = smu + st * ASTAGE_B;
        const uint32_t vB = kB + KTILE_B;

        float s[8][4];
        #pragma unroll
        for (int nf = 0; nf < 8; ++nf)
            #pragma unroll
            for (int c = 0; c < 4; ++c) s[nf][c] = 0.f;

        #pragma unroll
        for (int p = 0; p < 4; ++p) {
            uint32_t bf[2][2];
            #pragma unroll
            for (int ks = 0; ks < 4; ++ks) {
                uint32_t addr = kB
                    + (uint32_t)((2 * p + kq_sel) * 8 + kq_row) * KROW_B
                    + (uint32_t)(ks * 16 + kq_col * 8) * 2;
                ldsm_x4(bf[0][0], bf[0][1], bf[1][0], bf[1][1], addr);
                MMA_F16(s[2*p][0], s[2*p][1], s[2*p][2], s[2*p][3],
                        qa[ks][0], qa[ks][1], qa[ks][2], qa[ks][3],
                        bf[0][0], bf[0][1]);
                MMA_F16(s[2*p+1][0], s[2*p+1][1], s[2*p+1][2], s[2*p+1][3],
                        qa[ks][0], qa[ks][1], qa[ks][2], qa[ks][3],
                        bf[1][0], bf[1][1]);
            }
        }

        if (kt == ntile - 1) {
            const int r0l = w * 16 + g;
            #pragma unroll
            for (int nf = 0; nf < 8; ++nf) {
                const int c0 = nf * 8 + 2 * t;
                if (c0     > r0l)     s[nf][0] = -INFINITY;
                if (c0 + 1 > r0l)     s[nf][1] = -INFINITY;
                if (c0     > r0l + 8) s[nf][2] = -INFINITY;
                if (c0 + 1 > r0l + 8) s[nf][3] = -INFINITY;
            }
        }

        float tm0 = -INFINITY, tm1 = -INFINITY;
        #pragma unroll
        for (int nf = 0; nf < 8; ++nf) {
            tm0 = fmaxf(tm0, fmaxf(s[nf][0], s[nf][1]));
            tm1 = fmaxf(tm1, fmaxf(s[nf][2], s[nf][3]));
        }
        tm0 = fmaxf(tm0, __shfl_xor_sync(0xffffffffu, tm0, 1));
        tm0 = fmaxf(tm0, __shfl_xor_sync(0xffffffffu, tm0, 2));
        tm1 = fmaxf(tm1, __shfl_xor_sync(0xffffffffu, tm1, 1));
        tm1 = fmaxf(tm1, __shfl_xor_sync(0xffffffffu, tm1, 2));

        const float m0n = fmaxf(m0, tm0);
        const float m1n = fmaxf(m1, tm1);
        const float c0 = __expf(m0 - m0n);
        const float c1 = __expf(m1 - m1n);
        m0 = m0n; m1 = m1n;

        float ls0 = 0.f, ls1 = 0.f;
        #pragma unroll
        for (int nf = 0; nf < 8; ++nf) {
            s[nf][0] = __expf(s[nf][0] - m0n); ls0 += s[nf][0];
            s[nf][1] = __expf(s[nf][1] - m0n); ls0 += s[nf][1];
            s[nf][2] = __expf(s[nf][2] - m1n); ls1 += s[nf][2];
            s[nf][3] = __expf(s[nf][3] - m1n); ls1 += s[nf][3];
        }
        ls0 += __shfl_xor_sync(0xffffffffu, ls0, 1);
        ls0 += __shfl_xor_sync(0xffffffffu, ls0, 2);
        ls1 += __shfl_xor_sync(0xffffffffu, ls1, 1);
        ls1 += __shfl_xor_sync(0xffffffffu, ls1, 2);
        l0 = l0 * c0 + ls0;
        l1 = l1 * c1 + ls1;

        #pragma unroll
        for (int nf = 0; nf < 8; ++nf) {
            o[nf][0] *= c0; o[nf][1] *= c0;
            o[nf][2] *= c1; o[nf][3] *= c1;
        }

        uint32_t pa[4][4];
        #pragma unroll
        for (int ks = 0; ks < 4; ++ks) {
            pa[ks][0] = ph2(s[2 * ks][0],     s[2 * ks][1]);
            pa[ks][1] = ph2(s[2 * ks][2],     s[2 * ks][3]);
            pa[ks][2] = ph2(s[2 * ks + 1][0], s[2 * ks + 1][1]);
            pa[ks][3] = ph2(s[2 * ks + 1][2], s[2 * ks + 1][3]);
        }

        #pragma unroll
        for (int p = 0; p < 4; ++p) {
            #pragma unroll
            for (int ks = 0; ks < 4; ++ks) {
                uint32_t v0, v1, v2, v3;
                uint32_t addr = vB
                    + (uint32_t)(ks * 16 + v_row) * KROW_B
                    + (uint32_t)((2 * p + v_sel) * 8) * 2;
                ldsm_x4t(v0, v1, v2, v3, addr);
                MMA_F16(o[2*p][0], o[2*p][1], o[2*p][2], o[2*p][3],
                        pa[ks][0], pa[ks][1], pa[ks][2], pa[ks][3], v0, v1);
                MMA_F16(o[2*p+1][0], o[2*p+1][1], o[2*p+1][2], o[2*p+1][3],
                        pa[ks][0], pa[ks][1], pa[ks][2], pa[ks][3], v2, v3);
            }
        }
    }
    #undef LOAD_TILE

    const float inv0 = 1.f / l0;
    const float inv1 = 1.f / l1;
    const int gr0 = q0 + w * 16 + g;
    __half* op0 = out + ((size_t)b * SEQ + gr0) * EMB + h * HDIM;
    __half* op1 = op0 + 8 * EMB;
    #pragma unroll
    for (int nf = 0; nf < 8; ++nf) {
        const int col = nf * 8 + 2 * t;
        *reinterpret_cast<uint32_t*>(op0 + col) = ph2(o[nf][0] * inv0, o[nf][1] * inv0);
        *reinterpret_cast<uint32_t*>(op1 + col) = ph2(o[nf][2] * inv1, o[nf][3] * inv1);
    }
}

// ---------------------------------------------------------------------------
// Launch
// ---------------------------------------------------------------------------
extern "C" void kernel_launch(void* const* d_in, const int* in_sizes, int n_in,
                              void* d_out, int out_size)
{
    (void)in_sizes; (void)n_in; (void)out_size;
    const float* x     = (const float*)d_in[0];
    const float* W_qkv = (const float*)d_in[1];
    const float* b_qkv = (const float*)d_in[2];
    const float* W_o   = (const float*)d_in[3];
    const float* b_o   = (const float*)d_in[4];
    float* out = (float*)d_out;

    __half *xh = nullptr, *wqkvh = nullptr, *woh = nullptr;
    __half *qkvh = nullptr, *attnh = nullptr;
    cudaGetSymbolAddress((void**)&xh,    g_xh);
    cudaGetSymbolAddress((void**)&wqkvh, g_wqkvh);
    cudaGetSymbolAddress((void**)&woh,   g_woh);
    cudaGetSymbolAddress((void**)&qkvh,  g_qkvh);
    cudaGetSymbolAddress((void**)&attnh, g_attnh);

    cudaFuncSetAttribute(gemm_f16<__half>,
                         cudaFuncAttributeMaxDynamicSharedMemorySize, GSMEM);
    cudaFuncSetAttribute(gemm_f16<float>,
                         cudaFuncAttributeMaxDynamicSharedMemorySize, GSMEM);

    // 0) pre-pass conversions
    f32_to_f16<<<(M_ROWS * EMB / 4 + 255) / 256, 256>>>(x, xh, M_ROWS * EMB / 4);
    f32_to_f16<<<(3 * EMB * EMB / 4 + 255) / 256, 256>>>(W_qkv, wqkvh, 3 * EMB * EMB / 4);
    f32_to_f16<<<(EMB * EMB / 4 + 255) / 256, 256>>>(W_o, woh, EMB * EMB / 4);

    // 1) QKV projection (f16 out): grid (24, 32)
    gemm_f16<__half><<<dim3(3 * EMB / GBN, M_ROWS / GBM), 512, GSMEM>>>(
        xh, wqkvh, b_qkv, qkvh, M_ROWS, 3 * EMB, EMB);

    // 2) f16 causal flash attention
    attn_f16<<<dim3(SEQ / 64, HEADS, BATCH), 128, ASMEM>>>(attnh);

    // 3) Output projection (f32 out): grid (8, 32)
    gemm_f16<float><<<dim3(EMB / GBN, M_ROWS / GBM), 512, GSMEM>>>(
        attnh, woh, b_o, out, M_ROWS, EMB, EMB);
}

// round 12
// speedup vs baseline: 1.0360x; 1.0360x over previous
#include <cuda_runtime.h>
#include <cuda_fp16.h>
#include <math.h>
#include <stdint.h>
#include <stddef.h>

// Problem constants
#define BATCH 4
#define SEQ   2048
#define EMB   1024
#define HEADS 16
#define HDIM  64
#define M_ROWS (BATCH*SEQ)   // 8192

// Scratch (device globals — allocation-free per harness rules)
__device__ __half g_xh[(size_t)M_ROWS * EMB];        // x f16
__device__ __half g_wqkvh[(size_t)EMB * 3 * EMB];    // W_qkv f16 [K,N]
__device__ __half g_woh[(size_t)EMB * EMB];          // W_o f16 [K,N]
__device__ __half g_qkvh[(size_t)M_ROWS * 3 * EMB];  // qkv f16
__device__ __half g_attnh[(size_t)M_ROWS * EMB];     // attention out f16

// ---------------------------------------------------------------------------
// Helpers
// ---------------------------------------------------------------------------
__device__ __forceinline__ uint32_t ph2(float a, float b) {
    __half2 h = __floats2half2_rn(a, b);
    return *reinterpret_cast<uint32_t*>(&h);
}
__device__ __forceinline__ uint32_t s2u(const void* p) {
    uint32_t r;
    asm("{ .reg .u64 t; cvta.to.shared.u64 t, %1; cvt.u32.u64 %0, t; }"
        : "=r"(r) : "l"(p));
    return r;
}

#define MMA_F16(d0,d1,d2,d3, a0,a1,a2,a3, b0,b1)                            \
    asm volatile(                                                           \
        "mma.sync.aligned.m16n8k16.row.col.f32.f16.f16.f32 "                \
        "{%0,%1,%2,%3}, {%4,%5,%6,%7}, {%8,%9}, {%0,%1,%2,%3};"             \
        : "+f"(d0), "+f"(d1), "+f"(d2), "+f"(d3)                            \
        : "r"(a0), "r"(a1), "r"(a2), "r"(a3), "r"(b0), "r"(b1))

__device__ __forceinline__ void ldsm_x4(uint32_t& r0, uint32_t& r1,
                                        uint32_t& r2, uint32_t& r3, uint32_t addr) {
    asm volatile("ldmatrix.sync.aligned.m8n8.x4.shared.b16 {%0,%1,%2,%3}, [%4];"
                 : "=r"(r0), "=r"(r1), "=r"(r2), "=r"(r3) : "r"(addr));
}
__device__ __forceinline__ void ldsm_x4t(uint32_t& r0, uint32_t& r1,
                                         uint32_t& r2, uint32_t& r3, uint32_t addr) {
    asm volatile("ldmatrix.sync.aligned.m8n8.x4.trans.shared.b16 {%0,%1,%2,%3}, [%4];"
                 : "=r"(r0), "=r"(r1), "=r"(r2), "=r"(r3) : "r"(addr));
}
__device__ __forceinline__ void cp16(uint32_t dst, const void* src) {
    asm volatile("cp.async.cg.shared.global [%0], [%1], 16;"
                 :: "r"(dst), "l"(src) : "memory");
}
#define CP_COMMIT() asm volatile("cp.async.commit_group;" ::: "memory")
#define CP_WAIT(n)  asm volatile("cp.async.wait_group %0;" :: "n"(n) : "memory")

// ---------------------------------------------------------------------------
// Pre-pass: f32 -> f16
// ---------------------------------------------------------------------------
__global__ __launch_bounds__(256)
void f32_to_f16(const float* __restrict__ in, __half* __restrict__ out, int n4) {
    int i = blockIdx.x * 256 + threadIdx.x;
    if (i < n4) {
        float4 v = reinterpret_cast<const float4*>(in)[i];
        uint2 o = make_uint2(ph2(v.x, v.y), ph2(v.z, v.w));
        reinterpret_cast<uint2*>(out)[i] = o;
    }
}

// ---------------------------------------------------------------------------
// f16 tensor-core GEMM (exact R10 config): C = A[M,K] @ B[K,N] + bias
// CTA 128x128x64, 256 threads / 8 warps, warp tile 64x32, 2-stage cp.async.
// ---------------------------------------------------------------------------
#define GBM 128
#define GBN 128
#define GBK 64
#define APAD_B 144                  // bytes per A row (128 data + 16 pad)
#define BPAD_B 272                  // bytes per B row (256 data + 16 pad)
#define ASTG_B (GBM * APAD_B)       // 18432 B
#define BSTG_B (GBK * BPAD_B)       // 17408 B
#define GSMEM (2 * (ASTG_B + BSTG_B))   // 71680 B

template <typename OutT>
__global__ __launch_bounds__(256)
void gemm_f16(const __half* __restrict__ A, const __half* __restrict__ B,
              const float* __restrict__ bias, OutT* __restrict__ C,
              int M, int N, int K)
{
    extern __shared__ __align__(16) char smem[];
    const int tid  = threadIdx.x;
    const int wid  = tid >> 5;
    const int lane = tid & 31;
    const int g = lane >> 2;
    const int t = lane & 3;
    const int wm = (wid >> 2) * 64;   // 0 / 64
    const int wn = (wid & 3) * 32;    // 0/32/64/96
    const int n0 = blockIdx.x * GBN;
    const int m0 = blockIdx.y * GBM;

    const uint32_t smA_u = s2u(smem);
    const uint32_t smB_u = smA_u + 2 * ASTG_B;

    const __half* Ab = A + (size_t)m0 * K;
    const __half* Bb = B + n0;

    float acc[4][4][4];
    #pragma unroll
    for (int i = 0; i < 4; ++i)
        #pragma unroll
        for (int j = 0; j < 4; ++j)
            #pragma unroll
            for (int c = 0; c < 4; ++c) acc[i][j][c] = 0.f;

    const int ntiles = K / GBK;

    #define LOAD_CHUNK(kc, st) do {                                              \
        const int _k0 = (kc) * GBK;                                              \
        const uint32_t _aB = smA_u + (st) * ASTG_B;                              \
        const uint32_t _bB = smB_u + (st) * BSTG_B;                              \
        _Pragma("unroll")                                                        \
        for (int _i = 0; _i < 4; ++_i) {                                         \
            int _idx = tid + _i * 256;                                           \
            int _ar = _idx >> 3, _ac = _idx & 7;                                 \
            cp16(_aB + _ar * APAD_B + _ac * 16,                                  \
                 Ab + (size_t)_ar * K + _k0 + _ac * 8);                          \
            int _br = _idx >> 4, _bc = _idx & 15;                                \
            cp16(_bB + _br * BPAD_B + _bc * 16,                                  \
                 Bb + (size_t)(_k0 + _br) * N + _bc * 8);                        \
        }                                                                        \
        CP_COMMIT();                                                             \
    } while (0)

    LOAD_CHUNK(0, 0);

    for (int kt = 0; kt < ntiles; ++kt) {
        const int s = kt & 1;
        if (kt + 1 < ntiles) {
            LOAD_CHUNK(kt + 1, s ^ 1);
            CP_WAIT(1);
        } else {
            CP_WAIT(0);
        }
        __syncthreads();

        const uint32_t aS = smA_u + s * ASTG_B;
        const uint32_t bS = smB_u + s * BSTG_B;

        #pragma unroll
        for (int ks = 0; ks < 4; ++ks) {
            uint32_t a[4][4], bfr[4][2];
            #pragma unroll
            for (int mf = 0; mf < 4; ++mf) {
                uint32_t addr = aS
                    + (uint32_t)(wm + mf * 16 + (lane & 15)) * APAD_B
                    + (uint32_t)(ks * 16 + ((lane >> 4) << 3)) * 2;
                ldsm_x4(a[mf][0], a[mf][1], a[mf][2], a[mf][3], addr);
            }
            #pragma unroll
            for (int p = 0; p < 2; ++p) {
                uint32_t addr = bS
                    + (uint32_t)(ks * 16 + (lane & 15)) * BPAD_B
                    + (uint32_t)(wn + p * 16 + ((lane >> 4) << 3)) * 2;
                ldsm_x4t(bfr[2 * p][0], bfr[2 * p][1],
                         bfr[2 * p + 1][0], bfr[2 * p + 1][1], addr);
            }
            #pragma unroll
            for (int mf = 0; mf < 4; ++mf)
                #pragma unroll
                for (int nf = 0; nf < 4; ++nf)
                    MMA_F16(acc[mf][nf][0], acc[mf][nf][1],
                            acc[mf][nf][2], acc[mf][nf][3],
                            a[mf][0], a[mf][1], a[mf][2], a[mf][3],
                            bfr[nf][0], bfr[nf][1]);
        }
        __syncthreads();
    }
    #undef LOAD_CHUNK

    #pragma unroll
    for (int mf = 0; mf < 4; ++mf) {
        const int row = m0 + wm + mf * 16 + g;
        #pragma unroll
        for (int nf = 0; nf < 4; ++nf) {
            const int col = n0 + wn + nf * 8 + 2 * t;
            float2 b2 = *reinterpret_cast<const float2*>(bias + col);
            float o00 = acc[mf][nf][0] + b2.x, o01 = acc[mf][nf][1] + b2.y;
            float o10 = acc[mf][nf][2] + b2.x, o11 = acc[mf][nf][3] + b2.y;
            if (sizeof(OutT) == 2) {
                __half* p0 = (__half*)C + (size_t)row * N + col;
                __half* p1 = (__half*)C + (size_t)(row + 8) * N + col;
                *reinterpret_cast<uint32_t*>(p0) = ph2(o00, o01);
                *reinterpret_cast<uint32_t*>(p1) = ph2(o10, o11);
            } else {
                float* p0 = (float*)C + (size_t)row * N + col;
                float* p1 = (float*)C + (size_t)(row + 8) * N + col;
                *reinterpret_cast<float2*>(p0) = make_float2(o00, o01);
                *reinterpret_cast<float2*>(p1) = make_float2(o10, o11);
            }
        }
    }
}

// ---------------------------------------------------------------------------
// f16 causal flash attention — 128-query CTA, 8 warps (256 threads).
// Each 64-key K/V tile now serves 8 warps (halved global K/V traffic).
// Per-warp datapath identical to R10; mask is warp-relative.
// ---------------------------------------------------------------------------
#define KSTH 72                      // halves per row (64 + 8 pad) -> 144 B
#define KROW_B (KSTH * 2)            // 144
#define KTILE_B (64 * KROW_B)        // 9216 per matrix
#define ASTAGE_B (2 * KTILE_B)       // K + V per stage: 18432
#define ASMEM (2 * ASTAGE_B)         // 36864

__global__ __launch_bounds__(256)
void attn_f16(__half* __restrict__ out)
{
    extern __shared__ __align__(16) char asmem[];
    const int b  = blockIdx.z;
    const int h  = blockIdx.y;
    const int qt = blockIdx.x;
    const int tid  = threadIdx.x;
    const int w    = tid >> 5;          // 0..7
    const int lane = tid & 31;
    const int g = lane >> 2;
    const int t = lane & 3;
    const int q0 = qt * 128;
    const int wq0 = q0 + w * 16;        // warp's first query row

    const size_t row3E = (size_t)3 * EMB;
    const __half* basep = g_qkvh + (size_t)b * SEQ * row3E;
    const uint32_t smu = s2u(asmem);

    // Q fragments (f16x2, pre-scaled by 1/8 — exact in f16)
    uint32_t qa[4][4];
    {
        const __half2 sc = __half2half2(__float2half_rn(0.125f));
        const __half* q0p = basep + (size_t)(wq0 + g) * row3E + h * HDIM;
        const __half* q8p = q0p + 8 * row3E;
        #pragma unroll
        for (int ks = 0; ks < 4; ++ks) {
            __half2 v0 = *reinterpret_cast<const __half2*>(q0p + ks * 16 + 2 * t);
            __half2 v1 = *reinterpret_cast<const __half2*>(q8p + ks * 16 + 2 * t);
            __half2 v2 = *reinterpret_cast<const __half2*>(q0p + ks * 16 + 8 + 2 * t);
            __half2 v3 = *reinterpret_cast<const __half2*>(q8p + ks * 16 + 8 + 2 * t);
            v0 = __hmul2(v0, sc); v1 = __hmul2(v1, sc);
            v2 = __hmul2(v2, sc); v3 = __hmul2(v3, sc);
            qa[ks][0] = *reinterpret_cast<uint32_t*>(&v0);
            qa[ks][1] = *reinterpret_cast<uint32_t*>(&v1);
            qa[ks][2] = *reinterpret_cast<uint32_t*>(&v2);
            qa[ks][3] = *reinterpret_cast<uint32_t*>(&v3);
        }
    }

    float m0 = -INFINITY, m1 = -INFINITY, l0 = 0.f, l1 = 0.f;
    float o[8][4];
    #pragma unroll
    for (int nf = 0; nf < 8; ++nf)
        #pragma unroll
        for (int c = 0; c < 4; ++c) o[nf][c] = 0.f;

    // K/V tile loader: 64 rows x 128 B per matrix; 256 threads x 2 iters
    #define LOAD_TILE(kt_, st_) do {                                             \
        const int _k0 = (kt_) * 64;                                              \
        const uint32_t _kB = smu + (st_) * ASTAGE_B;                             \
        const uint32_t _vB = _kB + KTILE_B;                                      \
        _Pragma("unroll")                                                        \
        for (int _i = 0; _i < 2; ++_i) {                                         \
            int _idx = tid + _i * 256;                                           \
            int _r = _idx >> 3;                                                  \
            int _cb = (_idx & 7) << 4;                                           \
            const __half* _rp = basep + (size_t)(_k0 + _r) * row3E + h * HDIM;   \
            cp16(_kB + _r * KROW_B + _cb, (const char*)(_rp + EMB) + _cb);       \
            cp16(_vB + _r * KROW_B + _cb, (const char*)(_rp + 2 * EMB) + _cb);   \
        }                                                                        \
        CP_COMMIT();                                                             \
    } while (0)

    const int ntile = q0 / 64 + 2;   // keys up to q0+127
    LOAD_TILE(0, 0);

    const int kq_row = lane & 7;
    const int kq_sel = (lane >> 4) & 1;
    const int kq_col = (lane >> 3) & 1;
    const int v_row = lane & 15;
    const int v_sel = (lane >> 4) & 1;

    for (int kt = 0; kt < ntile; ++kt) {
        const int st = kt & 1;
        const int k0 = kt * 64;
        if (kt + 1 < ntile) { CP_WAIT(1); } else { CP_WAIT(0); }
        __syncthreads();
        if (kt + 1 < ntile) LOAD_TILE(kt + 1, st ^ 1);

        const uint32_t kB = smu + st * ASTAGE_B;
        const uint32_t vB = kB + KTILE_B;

        float s[8][4];
        #pragma unroll
        for (int nf = 0; nf < 8; ++nf)
            #pragma unroll
            for (int c = 0; c < 4; ++c) s[nf][c] = 0.f;

        #pragma unroll
        for (int p = 0; p < 4; ++p) {
            uint32_t bf[2][2];
            #pragma unroll
            for (int ks = 0; ks < 4; ++ks) {
                uint32_t addr = kB
                    + (uint32_t)((2 * p + kq_sel) * 8 + kq_row) * KROW_B
                    + (uint32_t)(ks * 16 + kq_col * 8) * 2;
                ldsm_x4(bf[0][0], bf[0][1], bf[1][0], bf[1][1], addr);
                MMA_F16(s[2*p][0], s[2*p][1], s[2*p][2], s[2*p][3],
                        qa[ks][0], qa[ks][1], qa[ks][2], qa[ks][3],
                        bf[0][0], bf[0][1]);
                MMA_F16(s[2*p+1][0], s[2*p+1][1], s[2*p+1][2], s[2*p+1][3],
                        qa[ks][0], qa[ks][1], qa[ks][2], qa[ks][3],
                        bf[1][0], bf[1][1]);
            }
        }

        // causal mask — warp-relative (tiles overlapping this warp's rows)
        if (k0 + 63 > wq0) {
            const int r0g = wq0 + g;
            #pragma unroll
            for (int nf = 0; nf < 8; ++nf) {
                const int cg = k0 + nf * 8 + 2 * t;
                if (cg     > r0g)     s[nf][0] = -INFINITY;
                if (cg + 1 > r0g)     s[nf][1] = -INFINITY;
                if (cg     > r0g + 8) s[nf][2] = -INFINITY;
                if (cg + 1 > r0g + 8) s[nf][3] = -INFINITY;
            }
        }

        float tm0 = -INFINITY, tm1 = -INFINITY;
        #pragma unroll
        for (int nf = 0; nf < 8; ++nf) {
            tm0 = fmaxf(tm0, fmaxf(s[nf][0], s[nf][1]));
            tm1 = fmaxf(tm1, fmaxf(s[nf][2], s[nf][3]));
        }
        tm0 = fmaxf(tm0, __shfl_xor_sync(0xffffffffu, tm0, 1));
        tm0 = fmaxf(tm0, __shfl_xor_sync(0xffffffffu, tm0, 2));
        tm1 = fmaxf(tm1, __shfl_xor_sync(0xffffffffu, tm1, 1));
        tm1 = fmaxf(tm1, __shfl_xor_sync(0xffffffffu, tm1, 2));

        const float m0n = fmaxf(m0, tm0);
        const float m1n = fmaxf(m1, tm1);
        const float c0 = __expf(m0 - m0n);
        const float c1 = __expf(m1 - m1n);
        m0 = m0n; m1 = m1n;

        float ls0 = 0.f, ls1 = 0.f;
        #pragma unroll
        for (int nf = 0; nf < 8; ++nf) {
            s[nf][0] = __expf(s[nf][0] - m0n); ls0 += s[nf][0];
            s[nf][1] = __expf(s[nf][1] - m0n); ls0 += s[nf][1];
            s[nf][2] = __expf(s[nf][2] - m1n); ls1 += s[nf][2];
            s[nf][3] = __expf(s[nf][3] - m1n); ls1 += s[nf][3];
        }
        ls0 += __shfl_xor_sync(0xffffffffu, ls0, 1);
        ls0 += __shfl_xor_sync(0xffffffffu, ls0, 2);
        ls1 += __shfl_xor_sync(0xffffffffu, ls1, 1);
        ls1 += __shfl_xor_sync(0xffffffffu, ls1, 2);
        l0 = l0 * c0 + ls0;
        l1 = l1 * c1 + ls1;

        #pragma unroll
        for (int nf = 0; nf < 8; ++nf) {
            o[nf][0] *= c0; o[nf][1] *= c0;
            o[nf][2] *= c1; o[nf][3] *= c1;
        }

        uint32_t pa[4][4];
        #pragma unroll
        for (int ks = 0; ks < 4; ++ks) {
            pa[ks][0] = ph2(s[2 * ks][0],     s[2 * ks][1]);
            pa[ks][1] = ph2(s[2 * ks][2],     s[2 * ks][3]);
            pa[ks][2] = ph2(s[2 * ks + 1][0], s[2 * ks + 1][1]);
            pa[ks][3] = ph2(s[2 * ks + 1][2], s[2 * ks + 1][3]);
        }

        #pragma unroll
        for (int p = 0; p < 4; ++p) {
            #pragma unroll
            for (int ks = 0; ks < 4; ++ks) {
                uint32_t v0, v1, v2, v3;
                uint32_t addr = vB
                    + (uint32_t)(ks * 16 + v_row) * KROW_B
                    + (uint32_t)((2 * p + v_sel) * 8) * 2;
                ldsm_x4t(v0, v1, v2, v3, addr);
                MMA_F16(o[2*p][0], o[2*p][1], o[2*p][2], o[2*p][3],
                        pa[ks][0], pa[ks][1], pa[ks][2], pa[ks][3], v0, v1);
                MMA_F16(o[2*p+1][0], o[2*p+1][1], o[2*p+1][2], o[2*p+1][3],
                        pa[ks][0], pa[ks][1], pa[ks][2], pa[ks][3], v2, v3);
            }
        }
    }
    #undef LOAD_TILE

    const float inv0 = 1.f / l0;
    const float inv1 = 1.f / l1;
    const int gr0 = wq0 + g;
    __half* op0 = out + ((size_t)b * SEQ + gr0) * EMB + h * HDIM;
    __half* op1 = op0 + 8 * EMB;
    #pragma unroll
    for (int nf = 0; nf < 8; ++nf) {
        const int col = nf * 8 + 2 * t;
        *reinterpret_cast<uint32_t*>(op0 + col) = ph2(o[nf][0] * inv0, o[nf][1] * inv0);
        *reinterpret_cast<uint32_t*>(op1 + col) = ph2(o[nf][2] * inv1, o[nf][3] * inv1);
    }
}

// ---------------------------------------------------------------------------
// Launch
// ---------------------------------------------------------------------------
extern "C" void kernel_launch(void* const* d_in, const int* in_sizes, int n_in,
                              void* d_out, int out_size)
{
    (void)in_sizes; (void)n_in; (void)out_size;
    const float* x     = (const float*)d_in[0];
    const float* W_qkv = (const float*)d_in[1];
    const float* b_qkv = (const float*)d_in[2];
    const float* W_o   = (const float*)d_in[3];
    const float* b_o   = (const float*)d_in[4];
    float* out = (float*)d_out;

    __half *xh = nullptr, *wqkvh = nullptr, *woh = nullptr;
    __half *qkvh = nullptr, *attnh = nullptr;
    cudaGetSymbolAddress((void**)&xh,    g_xh);
    cudaGetSymbolAddress((void**)&wqkvh, g_wqkvh);
    cudaGetSymbolAddress((void**)&woh,   g_woh);
    cudaGetSymbolAddress((void**)&qkvh,  g_qkvh);
    cudaGetSymbolAddress((void**)&attnh, g_attnh);

    cudaFuncSetAttribute(gemm_f16<__half>,
                         cudaFuncAttributeMaxDynamicSharedMemorySize, GSMEM);
    cudaFuncSetAttribute(gemm_f16<float>,
                         cudaFuncAttributeMaxDynamicSharedMemorySize, GSMEM);

    // 0) pre-pass conversions
    f32_to_f16<<<(M_ROWS * EMB / 4 + 255) / 256, 256>>>(x, xh, M_ROWS * EMB / 4);
    f32_to_f16<<<(3 * EMB * EMB / 4 + 255) / 256, 256>>>(W_qkv, wqkvh, 3 * EMB * EMB / 4);
    f32_to_f16<<<(EMB * EMB / 4 + 255) / 256, 256>>>(W_o, woh, EMB * EMB / 4);

    // 1) QKV projection (f16 out)
    gemm_f16<__half><<<dim3(3 * EMB / GBN, M_ROWS / GBM), 256, GSMEM>>>(
        xh, wqkvh, b_qkv, qkvh, M_ROWS, 3 * EMB, EMB);

    // 2) f16 causal flash attention (128-query CTAs, 8 warps)
    attn_f16<<<dim3(SEQ / 128, HEADS, BATCH), 256, ASMEM>>>(attnh);

    // 3) Output projection (f32 out)
    gemm_f16<float><<<dim3(EMB / GBN, M_ROWS / GBM), 256, GSMEM>>>(
        attnh, woh, b_o, out, M_ROWS, EMB, EMB);
}

// round 13
// speedup vs baseline: 1.0533x; 1.0167x over previous
#include <cuda_runtime.h>
#include <cuda_fp16.h>
#include <math.h>
#include <stdint.h>
#include <stddef.h>

// Problem constants
#define BATCH 4
#define SEQ   2048
#define EMB   1024
#define HEADS 16
#define HDIM  64
#define M_ROWS (BATCH*SEQ)   // 8192

// Scratch (device globals — allocation-free per harness rules)
__device__ __half g_xh[(size_t)M_ROWS * EMB];        // x f16
__device__ __half g_wqkvh[(size_t)EMB * 3 * EMB];    // W_qkv f16 [K,N]
__device__ __half g_woh[(size_t)EMB * EMB];          // W_o f16 [K,N]
__device__ __half g_qkvh[(size_t)M_ROWS * 3 * EMB];  // qkv f16
__device__ __half g_attnh[(size_t)M_ROWS * EMB];     // attention out f16

// ---------------------------------------------------------------------------
// Helpers
// ---------------------------------------------------------------------------
__device__ __forceinline__ uint32_t ph2(float a, float b) {
    __half2 h = __floats2half2_rn(a, b);
    return *reinterpret_cast<uint32_t*>(&h);
}
__device__ __forceinline__ uint32_t s2u(const void* p) {
    uint32_t r;
    asm("{ .reg .u64 t; cvta.to.shared.u64 t, %1; cvt.u32.u64 %0, t; }"
        : "=r"(r) : "l"(p));
    return r;
}

#define MMA_F16(d0,d1,d2,d3, a0,a1,a2,a3, b0,b1)                            \
    asm volatile(                                                           \
        "mma.sync.aligned.m16n8k16.row.col.f32.f16.f16.f32 "                \
        "{%0,%1,%2,%3}, {%4,%5,%6,%7}, {%8,%9}, {%0,%1,%2,%3};"             \
        : "+f"(d0), "+f"(d1), "+f"(d2), "+f"(d3)                            \
        : "r"(a0), "r"(a1), "r"(a2), "r"(a3), "r"(b0), "r"(b1))

__device__ __forceinline__ void ldsm_x4(uint32_t& r0, uint32_t& r1,
                                        uint32_t& r2, uint32_t& r3, uint32_t addr) {
    asm volatile("ldmatrix.sync.aligned.m8n8.x4.shared.b16 {%0,%1,%2,%3}, [%4];"
                 : "=r"(r0), "=r"(r1), "=r"(r2), "=r"(r3) : "r"(addr));
}
__device__ __forceinline__ void ldsm_x4t(uint32_t& r0, uint32_t& r1,
                                         uint32_t& r2, uint32_t& r3, uint32_t addr) {
    asm volatile("ldmatrix.sync.aligned.m8n8.x4.trans.shared.b16 {%0,%1,%2,%3}, [%4];"
                 : "=r"(r0), "=r"(r1), "=r"(r2), "=r"(r3) : "r"(addr));
}
__device__ __forceinline__ void cp16(uint32_t dst, const void* src) {
    asm volatile("cp.async.cg.shared.global [%0], [%1], 16;"
                 :: "r"(dst), "l"(src) : "memory");
}
#define CP_COMMIT() asm volatile("cp.async.commit_group;" ::: "memory")
#define CP_WAIT(n)  asm volatile("cp.async.wait_group %0;" :: "n"(n) : "memory")

// ---------------------------------------------------------------------------
// Pre-pass: f32 -> f16
// ---------------------------------------------------------------------------
__global__ __launch_bounds__(256)
void f32_to_f16(const float* __restrict__ in, __half* __restrict__ out, int n4) {
    int i = blockIdx.x * 256 + threadIdx.x;
    if (i < n4) {
        float4 v = reinterpret_cast<const float4*>(in)[i];
        uint2 o = make_uint2(ph2(v.x, v.y), ph2(v.z, v.w));
        reinterpret_cast<uint2*>(out)[i] = o;
    }
}

// ---------------------------------------------------------------------------
// f16 tensor-core GEMM (exact R10 config): C = A[M,K] @ B[K,N] + bias
// CTA 128x128x64, 256 threads / 8 warps, warp tile 64x32, 2-stage cp.async.
// ---------------------------------------------------------------------------
#define GBM 128
#define GBN 128
#define GBK 64
#define APAD_B 144
#define BPAD_B 272
#define ASTG_B (GBM * APAD_B)       // 18432 B
#define BSTG_B (GBK * BPAD_B)       // 17408 B
#define GSMEM (2 * (ASTG_B + BSTG_B))   // 71680 B

template <typename OutT>
__global__ __launch_bounds__(256)
void gemm_f16(const __half* __restrict__ A, const __half* __restrict__ B,
              const float* __restrict__ bias, OutT* __restrict__ C,
              int M, int N, int K)
{
    extern __shared__ __align__(16) char smem[];
    const int tid  = threadIdx.x;
    const int wid  = tid >> 5;
    const int lane = tid & 31;
    const int g = lane >> 2;
    const int t = lane & 3;
    const int wm = (wid >> 2) * 64;
    const int wn = (wid & 3) * 32;
    const int n0 = blockIdx.x * GBN;
    const int m0 = blockIdx.y * GBM;

    const uint32_t smA_u = s2u(smem);
    const uint32_t smB_u = smA_u + 2 * ASTG_B;

    const __half* Ab = A + (size_t)m0 * K;
    const __half* Bb = B + n0;

    float acc[4][4][4];
    #pragma unroll
    for (int i = 0; i < 4; ++i)
        #pragma unroll
        for (int j = 0; j < 4; ++j)
            #pragma unroll
            for (int c = 0; c < 4; ++c) acc[i][j][c] = 0.f;

    const int ntiles = K / GBK;

    #define LOAD_CHUNK(kc, st) do {                                              \
        const int _k0 = (kc) * GBK;                                              \
        const uint32_t _aB = smA_u + (st) * ASTG_B;                              \
        const uint32_t _bB = smB_u + (st) * BSTG_B;                              \
        _Pragma("unroll")                                                        \
        for (int _i = 0; _i < 4; ++_i) {                                         \
            int _idx = tid + _i * 256;                                           \
            int _ar = _idx >> 3, _ac = _idx & 7;                                 \
            cp16(_aB + _ar * APAD_B + _ac * 16,                                  \
                 Ab + (size_t)_ar * K + _k0 + _ac * 8);                          \
            int _br = _idx >> 4, _bc = _idx & 15;                                \
            cp16(_bB + _br * BPAD_B + _bc * 16,                                  \
                 Bb + (size_t)(_k0 + _br) * N + _bc * 8);                        \
        }                                                                        \
        CP_COMMIT();                                                             \
    } while (0)

    LOAD_CHUNK(0, 0);

    for (int kt = 0; kt < ntiles; ++kt) {
        const int s = kt & 1;
        if (kt + 1 < ntiles) {
            LOAD_CHUNK(kt + 1, s ^ 1);
            CP_WAIT(1);
        } else {
            CP_WAIT(0);
        }
        __syncthreads();

        const uint32_t aS = smA_u + s * ASTG_B;
        const uint32_t bS = smB_u + s * BSTG_B;

        #pragma unroll
        for (int ks = 0; ks < 4; ++ks) {
            uint32_t a[4][4], bfr[4][2];
            #pragma unroll
            for (int mf = 0; mf < 4; ++mf) {
                uint32_t addr = aS
                    + (uint32_t)(wm + mf * 16 + (lane & 15)) * APAD_B
                    + (uint32_t)(ks * 16 + ((lane >> 4) << 3)) * 2;
                ldsm_x4(a[mf][0], a[mf][1], a[mf][2], a[mf][3], addr);
            }
            #pragma unroll
            for (int p = 0; p < 2; ++p) {
                uint32_t addr = bS
                    + (uint32_t)(ks * 16 + (lane & 15)) * BPAD_B
                    + (uint32_t)(wn + p * 16 + ((lane >> 4) << 3)) * 2;
                ldsm_x4t(bfr[2 * p][0], bfr[2 * p][1],
                         bfr[2 * p + 1][0], bfr[2 * p + 1][1], addr);
            }
            #pragma unroll
            for (int mf = 0; mf < 4; ++mf)
                #pragma unroll
                for (int nf = 0; nf < 4; ++nf)
                    MMA_F16(acc[mf][nf][0], acc[mf][nf][1],
                            acc[mf][nf][2], acc[mf][nf][3],
                            a[mf][0], a[mf][1], a[mf][2], a[mf][3],
                            bfr[nf][0], bfr[nf][1]);
        }
        __syncthreads();
    }
    #undef LOAD_CHUNK

    #pragma unroll
    for (int mf = 0; mf < 4; ++mf) {
        const int row = m0 + wm + mf * 16 + g;
        #pragma unroll
        for (int nf = 0; nf < 4; ++nf) {
            const int col = n0 + wn + nf * 8 + 2 * t;
            float2 b2 = *reinterpret_cast<const float2*>(bias + col);
            float o00 = acc[mf][nf][0] + b2.x, o01 = acc[mf][nf][1] + b2.y;
            float o10 = acc[mf][nf][2] + b2.x, o11 = acc[mf][nf][3] + b2.y;
            if (sizeof(OutT) == 2) {
                __half* p0 = (__half*)C + (size_t)row * N + col;
                __half* p1 = (__half*)C + (size_t)(row + 8) * N + col;
                *reinterpret_cast<uint32_t*>(p0) = ph2(o00, o01);
                *reinterpret_cast<uint32_t*>(p1) = ph2(o10, o11);
            } else {
                float* p0 = (float*)C + (size_t)row * N + col;
                float* p1 = (float*)C + (size_t)(row + 8) * N + col;
                *reinterpret_cast<float2*>(p0) = make_float2(o00, o01);
                *reinterpret_cast<float2*>(p1) = make_float2(o10, o11);
            }
        }
    }
}

// ---------------------------------------------------------------------------
// f16 causal flash attention — 128-query CTA, 4 warps (128 threads).
// Each warp owns 32 query rows (two m16 fragments); K/V fragments are
// loaded once per (p,ks) and reused by both m-halves. K/V traffic halved
// vs 64-query CTAs. Warps skip tiles fully above their causal boundary.
// ---------------------------------------------------------------------------
#define KSTH 72                      // halves per row (64 + 8 pad) -> 144 B
#define KROW_B (KSTH * 2)            // 144
#define KTILE_B (64 * KROW_B)        // 9216 per matrix
#define ASTAGE_B (2 * KTILE_B)       // K + V per stage: 18432
#define ASMEM (2 * ASTAGE_B)         // 36864

__global__ __launch_bounds__(128)
void attn_f16(__half* __restrict__ out)
{
    extern __shared__ __align__(16) char asmem[];
    const int b  = blockIdx.z;
    const int h  = blockIdx.y;
    const int qt = blockIdx.x;
    const int tid  = threadIdx.x;
    const int w    = tid >> 5;          // 0..3
    const int lane = tid & 31;
    const int g = lane >> 2;
    const int t = lane & 3;
    const int q0 = qt * 128;
    const int wq0 = q0 + w * 32;        // warp's first query row (32 rows)

    const size_t row3E = (size_t)3 * EMB;
    const __half* basep = g_qkvh + (size_t)b * SEQ * row3E;
    const uint32_t smu = s2u(asmem);

    // Q fragments for two m16 halves (pre-scaled by 1/8 — exact in f16)
    uint32_t qa[2][4][4];
    {
        const __half2 sc = __half2half2(__float2half_rn(0.125f));
        #pragma unroll
        for (int mh = 0; mh < 2; ++mh) {
            const __half* q0p = basep + (size_t)(wq0 + mh * 16 + g) * row3E + h * HDIM;
            const __half* q8p = q0p + 8 * row3E;
            #pragma unroll
            for (int ks = 0; ks < 4; ++ks) {
                __half2 v0 = *reinterpret_cast<const __half2*>(q0p + ks * 16 + 2 * t);
                __half2 v1 = *reinterpret_cast<const __half2*>(q8p + ks * 16 + 2 * t);
                __half2 v2 = *reinterpret_cast<const __half2*>(q0p + ks * 16 + 8 + 2 * t);
                __half2 v3 = *reinterpret_cast<const __half2*>(q8p + ks * 16 + 8 + 2 * t);
                v0 = __hmul2(v0, sc); v1 = __hmul2(v1, sc);
                v2 = __hmul2(v2, sc); v3 = __hmul2(v3, sc);
                qa[mh][ks][0] = *reinterpret_cast<uint32_t*>(&v0);
                qa[mh][ks][1] = *reinterpret_cast<uint32_t*>(&v1);
                qa[mh][ks][2] = *reinterpret_cast<uint32_t*>(&v2);
                qa[mh][ks][3] = *reinterpret_cast<uint32_t*>(&v3);
            }
        }
    }

    float m0[2] = {-INFINITY, -INFINITY}, m1[2] = {-INFINITY, -INFINITY};
    float l0[2] = {0.f, 0.f}, l1[2] = {0.f, 0.f};
    float o[2][8][4];
    #pragma unroll
    for (int mh = 0; mh < 2; ++mh)
        #pragma unroll
        for (int nf = 0; nf < 8; ++nf)
            #pragma unroll
            for (int c = 0; c < 4; ++c) o[mh][nf][c] = 0.f;

    // K/V tile loader: 64 rows x 128 B per matrix; 128 threads x 4 iters
    #define LOAD_TILE(kt_, st_) do {                                             \
        const int _k0 = (kt_) * 64;                                              \
        const uint32_t _kB = smu + (st_) * ASTAGE_B;                             \
        const uint32_t _vB = _kB + KTILE_B;                                      \
        _Pragma("unroll")                                                        \
        for (int _i = 0; _i < 4; ++_i) {                                         \
            int _idx = tid + _i * 128;                                           \
            int _r = _idx >> 3;                                                  \
            int _cb = (_idx & 7) << 4;                                           \
            const __half* _rp = basep + (size_t)(_k0 + _r) * row3E + h * HDIM;   \
            cp16(_kB + _r * KROW_B + _cb, (const char*)(_rp + EMB) + _cb);       \
            cp16(_vB + _r * KROW_B + _cb, (const char*)(_rp + 2 * EMB) + _cb);   \
        }                                                                        \
        CP_COMMIT();                                                             \
    } while (0)

    const int ntile = q0 / 64 + 2;   // keys up to q0+127
    LOAD_TILE(0, 0);

    const int kq_row = lane & 7;
    const int kq_sel = (lane >> 4) & 1;
    const int kq_col = (lane >> 3) & 1;
    const int v_row = lane & 15;
    const int v_sel = (lane >> 4) & 1;

    for (int kt = 0; kt < ntile; ++kt) {
        const int st = kt & 1;
        const int k0 = kt * 64;
        if (kt + 1 < ntile) { CP_WAIT(1); } else { CP_WAIT(0); }
        __syncthreads();
        if (kt + 1 < ntile) LOAD_TILE(kt + 1, st ^ 1);

        // Skip tiles entirely above this warp's causal boundary
        if (k0 > wq0 + 31) continue;

        const uint32_t kB = smu + st * ASTAGE_B;
        const uint32_t vB = kB + KTILE_B;

        float s[2][8][4];
        #pragma unroll
        for (int mh = 0; mh < 2; ++mh)
            #pragma unroll
            for (int nf = 0; nf < 8; ++nf)
                #pragma unroll
                for (int c = 0; c < 4; ++c) s[mh][nf][c] = 0.f;

        // Scores: K frag loaded once, reused for both m-halves
        #pragma unroll
        for (int p = 0; p < 4; ++p) {
            #pragma unroll
            for (int ks = 0; ks < 4; ++ks) {
                uint32_t b0, b1, b2, b3;
                uint32_t addr = kB
                    + (uint32_t)((2 * p + kq_sel) * 8 + kq_row) * KROW_B
                    + (uint32_t)(ks * 16 + kq_col * 8) * 2;
                ldsm_x4(b0, b1, b2, b3, addr);
                #pragma unroll
                for (int mh = 0; mh < 2; ++mh) {
                    MMA_F16(s[mh][2*p][0], s[mh][2*p][1], s[mh][2*p][2], s[mh][2*p][3],
                            qa[mh][ks][0], qa[mh][ks][1], qa[mh][ks][2], qa[mh][ks][3],
                            b0, b1);
                    MMA_F16(s[mh][2*p+1][0], s[mh][2*p+1][1], s[mh][2*p+1][2], s[mh][2*p+1][3],
                            qa[mh][ks][0], qa[mh][ks][1], qa[mh][ks][2], qa[mh][ks][3],
                            b2, b3);
                }
            }
        }

        // Causal mask per m-half (tiles overlapping that half's rows)
        #pragma unroll
        for (int mh = 0; mh < 2; ++mh) {
            const int base = wq0 + mh * 16;
            if (k0 + 63 > base) {
                const int r0g = base + g;
                #pragma unroll
                for (int nf = 0; nf < 8; ++nf) {
                    const int cg = k0 + nf * 8 + 2 * t;
                    if (cg     > r0g)     s[mh][nf][0] = -INFINITY;
                    if (cg + 1 > r0g)     s[mh][nf][1] = -INFINITY;
                    if (cg     > r0g + 8) s[mh][nf][2] = -INFINITY;
                    if (cg + 1 > r0g + 8) s[mh][nf][3] = -INFINITY;
                }
            }
        }

        // Online softmax per m-half
        uint32_t pa[2][4][4];
        #pragma unroll
        for (int mh = 0; mh < 2; ++mh) {
            float tm0 = -INFINITY, tm1 = -INFINITY;
            #pragma unroll
            for (int nf = 0; nf < 8; ++nf) {
                tm0 = fmaxf(tm0, fmaxf(s[mh][nf][0], s[mh][nf][1]));
                tm1 = fmaxf(tm1, fmaxf(s[mh][nf][2], s[mh][nf][3]));
            }
            tm0 = fmaxf(tm0, __shfl_xor_sync(0xffffffffu, tm0, 1));
            tm0 = fmaxf(tm0, __shfl_xor_sync(0xffffffffu, tm0, 2));
            tm1 = fmaxf(tm1, __shfl_xor_sync(0xffffffffu, tm1, 1));
            tm1 = fmaxf(tm1, __shfl_xor_sync(0xffffffffu, tm1, 2));

            const float m0n = fmaxf(m0[mh], tm0);
            const float m1n = fmaxf(m1[mh], tm1);
            const float c0 = __expf(m0[mh] - m0n);
            const float c1 = __expf(m1[mh] - m1n);
            m0[mh] = m0n; m1[mh] = m1n;

            float ls0 = 0.f, ls1 = 0.f;
            #pragma unroll
            for (int nf = 0; nf < 8; ++nf) {
                s[mh][nf][0] = __expf(s[mh][nf][0] - m0n); ls0 += s[mh][nf][0];
                s[mh][nf][1] = __expf(s[mh][nf][1] - m0n); ls0 += s[mh][nf][1];
                s[mh][nf][2] = __expf(s[mh][nf][2] - m1n); ls1 += s[mh][nf][2];
                s[mh][nf][3] = __expf(s[mh][nf][3] - m1n); ls1 += s[mh][nf][3];
            }
            ls0 += __shfl_xor_sync(0xffffffffu, ls0, 1);
            ls0 += __shfl_xor_sync(0xffffffffu, ls0, 2);
            ls1 += __shfl_xor_sync(0xffffffffu, ls1, 1);
            ls1 += __shfl_xor_sync(0xffffffffu, ls1, 2);
            l0[mh] = l0[mh] * c0 + ls0;
            l1[mh] = l1[mh] * c1 + ls1;

            #pragma unroll
            for (int nf = 0; nf < 8; ++nf) {
                o[mh][nf][0] *= c0; o[mh][nf][1] *= c0;
                o[mh][nf][2] *= c1; o[mh][nf][3] *= c1;
            }

            #pragma unroll
            for (int ks = 0; ks < 4; ++ks) {
                pa[mh][ks][0] = ph2(s[mh][2 * ks][0],     s[mh][2 * ks][1]);
                pa[mh][ks][1] = ph2(s[mh][2 * ks][2],     s[mh][2 * ks][3]);
                pa[mh][ks][2] = ph2(s[mh][2 * ks + 1][0], s[mh][2 * ks + 1][1]);
                pa[mh][ks][3] = ph2(s[mh][2 * ks + 1][2], s[mh][2 * ks + 1][3]);
            }
        }

        // O += P @ V — V frag loaded once, reused for both m-halves
        #pragma unroll
        for (int p = 0; p < 4; ++p) {
            #pragma unroll
            for (int ks = 0; ks < 4; ++ks) {
                uint32_t v0, v1, v2, v3;
                uint32_t addr = vB
                    + (uint32_t)(ks * 16 + v_row) * KROW_B
                    + (uint32_t)((2 * p + v_sel) * 8) * 2;
                ldsm_x4t(v0, v1, v2, v3, addr);
                #pragma unroll
                for (int mh = 0; mh < 2; ++mh) {
                    MMA_F16(o[mh][2*p][0], o[mh][2*p][1], o[mh][2*p][2], o[mh][2*p][3],
                            pa[mh][ks][0], pa[mh][ks][1], pa[mh][ks][2], pa[mh][ks][3],
                            v0, v1);
                    MMA_F16(o[mh][2*p+1][0], o[mh][2*p+1][1], o[mh][2*p+1][2], o[mh][2*p+1][3],
                            pa[mh][ks][0], pa[mh][ks][1], pa[mh][ks][2], pa[mh][ks][3],
                            v2, v3);
                }
            }
        }
    }
    #undef LOAD_TILE

    // Epilogue -> f16
    #pragma unroll
    for (int mh = 0; mh < 2; ++mh) {
        const float inv0 = 1.f / l0[mh];
        const float inv1 = 1.f / l1[mh];
        const int gr0 = wq0 + mh * 16 + g;
        __half* op0 = out + ((size_t)b * SEQ + gr0) * EMB + h * HDIM;
        __half* op1 = op0 + 8 * EMB;
        #pragma unroll
        for (int nf = 0; nf < 8; ++nf) {
            const int col = nf * 8 + 2 * t;
            *reinterpret_cast<uint32_t*>(op0 + col) =
                ph2(o[mh][nf][0] * inv0, o[mh][nf][1] * inv0);
            *reinterpret_cast<uint32_t*>(op1 + col) =
                ph2(o[mh][nf][2] * inv1, o[mh][nf][3] * inv1);
        }
    }
}

// ---------------------------------------------------------------------------
// Launch
// ---------------------------------------------------------------------------
extern "C" void kernel_launch(void* const* d_in, const int* in_sizes, int n_in,
                              void* d_out, int out_size)
{
    (void)in_sizes; (void)n_in; (void)out_size;
    const float* x     = (const float*)d_in[0];
    const float* W_qkv = (const float*)d_in[1];
    const float* b_qkv = (const float*)d_in[2];
    const float* W_o   = (const float*)d_in[3];
    const float* b_o   = (const float*)d_in[4];
    float* out = (float*)d_out;

    __half *xh = nullptr, *wqkvh = nullptr, *woh = nullptr;
    __half *qkvh = nullptr, *attnh = nullptr;
    cudaGetSymbolAddress((void**)&xh,    g_xh);
    cudaGetSymbolAddress((void**)&wqkvh, g_wqkvh);
    cudaGetSymbolAddress((void**)&woh,   g_woh);
    cudaGetSymbolAddress((void**)&qkvh,  g_qkvh);
    cudaGetSymbolAddress((void**)&attnh, g_attnh);

    cudaFuncSetAttribute(gemm_f16<__half>,
                         cudaFuncAttributeMaxDynamicSharedMemorySize, GSMEM);
    cudaFuncSetAttribute(gemm_f16<float>,
                         cudaFuncAttributeMaxDynamicSharedMemorySize, GSMEM);

    // 0) pre-pass conversions
    f32_to_f16<<<(M_ROWS * EMB / 4 + 255) / 256, 256>>>(x, xh, M_ROWS * EMB / 4);
    f32_to_f16<<<(3 * EMB * EMB / 4 + 255) / 256, 256>>>(W_qkv, wqkvh, 3 * EMB * EMB / 4);
    f32_to_f16<<<(EMB * EMB / 4 + 255) / 256, 256>>>(W_o, woh, EMB * EMB / 4);

    // 1) QKV projection (f16 out)
    gemm_f16<__half><<<dim3(3 * EMB / GBN, M_ROWS / GBM), 256, GSMEM>>>(
        xh, wqkvh, b_qkv, qkvh, M_ROWS, 3 * EMB, EMB);

    // 2) f16 causal flash attention (128-query CTAs, 4 warps, 32 rows/warp)
    attn_f16<<<dim3(SEQ / 128, HEADS, BATCH), 128, ASMEM>>>(attnh);

    // 3) Output projection (f32 out)
    gemm_f16<float><<<dim3(EMB / GBN, M_ROWS / GBM), 256, GSMEM>>>(
        attnh, woh, b_o, out, M_ROWS, EMB, EMB);
}

// round 14
// speedup vs baseline: 1.0876x; 1.0325x over previous
#include <cuda_runtime.h>
#include <cuda_fp16.h>
#include <math.h>
#include <stdint.h>
#include <stddef.h>

// Problem constants
#define BATCH 4
#define SEQ   2048
#define EMB   1024
#define HEADS 16
#define HDIM  64
#define M_ROWS (BATCH*SEQ)   // 8192

// Scratch (device globals — allocation-free per harness rules)
__device__ __half g_xh[(size_t)M_ROWS * EMB];        // x f16
__device__ __half g_wqkvh[(size_t)EMB * 3 * EMB];    // W_qkv f16 [K,N]
__device__ __half g_woh[(size_t)EMB * EMB];          // W_o f16 [K,N]
__device__ __half g_qkvh[(size_t)M_ROWS * 3 * EMB];  // qkv f16
__device__ __half g_attnh[(size_t)M_ROWS * EMB];     // attention out f16

// ---------------------------------------------------------------------------
// Helpers
// ---------------------------------------------------------------------------
__device__ __forceinline__ uint32_t ph2(float a, float b) {
    __half2 h = __floats2half2_rn(a, b);
    return *reinterpret_cast<uint32_t*>(&h);
}
__device__ __forceinline__ uint32_t s2u(const void* p) {
    uint32_t r;
    asm("{ .reg .u64 t; cvta.to.shared.u64 t, %1; cvt.u32.u64 %0, t; }"
        : "=r"(r) : "l"(p));
    return r;
}

#define MMA_F16(d0,d1,d2,d3, a0,a1,a2,a3, b0,b1)                            \
    asm volatile(                                                           \
        "mma.sync.aligned.m16n8k16.row.col.f32.f16.f16.f32 "                \
        "{%0,%1,%2,%3}, {%4,%5,%6,%7}, {%8,%9}, {%0,%1,%2,%3};"             \
        : "+f"(d0), "+f"(d1), "+f"(d2), "+f"(d3)                            \
        : "r"(a0), "r"(a1), "r"(a2), "r"(a3), "r"(b0), "r"(b1))

__device__ __forceinline__ void ldsm_x4(uint32_t& r0, uint32_t& r1,
                                        uint32_t& r2, uint32_t& r3, uint32_t addr) {
    asm volatile("ldmatrix.sync.aligned.m8n8.x4.shared.b16 {%0,%1,%2,%3}, [%4];"
                 : "=r"(r0), "=r"(r1), "=r"(r2), "=r"(r3) : "r"(addr));
}
__device__ __forceinline__ void ldsm_x4t(uint32_t& r0, uint32_t& r1,
                                         uint32_t& r2, uint32_t& r3, uint32_t addr) {
    asm volatile("ldmatrix.sync.aligned.m8n8.x4.trans.shared.b16 {%0,%1,%2,%3}, [%4];"
                 : "=r"(r0), "=r"(r1), "=r"(r2), "=r"(r3) : "r"(addr));
}
__device__ __forceinline__ void cp16(uint32_t dst, const void* src) {
    asm volatile("cp.async.cg.shared.global [%0], [%1], 16;"
                 :: "r"(dst), "l"(src) : "memory");
}
#define CP_COMMIT() asm volatile("cp.async.commit_group;" ::: "memory")
#define CP_WAIT(n)  asm volatile("cp.async.wait_group %0;" :: "n"(n) : "memory")

// ---------------------------------------------------------------------------
// Fused pre-pass: convert x, W_qkv, W_o to f16 in one launch.
// Total float4 count: x 2Mi + Wqkv 768Ki + Wo 256Ki = 3,145,728.
// ---------------------------------------------------------------------------
#define N4_X   (M_ROWS * EMB / 4)          // 2097152
#define N4_WQ  (3 * EMB * EMB / 4)         // 786432
#define N4_WO  (EMB * EMB / 4)             // 262144
#define N4_ALL (N4_X + N4_WQ + N4_WO)

__global__ __launch_bounds__(256)
void prepass_cvt(const float* __restrict__ x, const float* __restrict__ wq,
                 const float* __restrict__ wo)
{
    int i = blockIdx.x * 256 + threadIdx.x;
    const float* src;
    __half* dst;
    int j = i;
    if (j < N4_X)            { src = x;  dst = g_xh; }
    else if ((j -= N4_X) < N4_WQ)  { src = wq; dst = g_wqkvh; }
    else if ((j -= N4_WQ) < N4_WO) { src = wo; dst = g_woh; }
    else return;
    float4 v = reinterpret_cast<const float4*>(src)[j];
    uint2 o = make_uint2(ph2(v.x, v.y), ph2(v.z, v.w));
    reinterpret_cast<uint2*>(dst)[j] = o;
}

// ---------------------------------------------------------------------------
// f16 tensor-core GEMM: C = A[M,K] @ B[K,N] + bias
// CTA 128x128x64, 256 threads / 8 warps, warp tile 64x32, 2-stage cp.async,
// ONE __syncthreads per chunk (next-chunk loads issued post-sync into the
// stage computed on in iter kt-1 — barrier orders the WAR).
// ---------------------------------------------------------------------------
#define GBM 128
#define GBN 128
#define GBK 64
#define APAD_B 144
#define BPAD_B 272
#define ASTG_B (GBM * APAD_B)       // 18432 B
#define BSTG_B (GBK * BPAD_B)       // 17408 B
#define GSMEM (2 * (ASTG_B + BSTG_B))   // 71680 B

template <typename OutT>
__global__ __launch_bounds__(256)
void gemm_f16(const __half* __restrict__ A, const __half* __restrict__ B,
              const float* __restrict__ bias, OutT* __restrict__ C,
              int M, int N, int K)
{
    extern __shared__ __align__(16) char smem[];
    const int tid  = threadIdx.x;
    const int wid  = tid >> 5;
    const int lane = tid & 31;
    const int g = lane >> 2;
    const int t = lane & 3;
    const int wm = (wid >> 2) * 64;
    const int wn = (wid & 3) * 32;
    const int n0 = blockIdx.x * GBN;
    const int m0 = blockIdx.y * GBM;

    const uint32_t smA_u = s2u(smem);
    const uint32_t smB_u = smA_u + 2 * ASTG_B;

    const __half* Ab = A + (size_t)m0 * K;
    const __half* Bb = B + n0;

    float acc[4][4][4];
    #pragma unroll
    for (int i = 0; i < 4; ++i)
        #pragma unroll
        for (int j = 0; j < 4; ++j)
            #pragma unroll
            for (int c = 0; c < 4; ++c) acc[i][j][c] = 0.f;

    const int ntiles = K / GBK;

    #define LOAD_CHUNK(kc, st) do {                                              \
        const int _k0 = (kc) * GBK;                                              \
        const uint32_t _aB = smA_u + (st) * ASTG_B;                              \
        const uint32_t _bB = smB_u + (st) * BSTG_B;                              \
        _Pragma("unroll")                                                        \
        for (int _i = 0; _i < 4; ++_i) {                                         \
            int _idx = tid + _i * 256;                                           \
            int _ar = _idx >> 3, _ac = _idx & 7;                                 \
            cp16(_aB + _ar * APAD_B + _ac * 16,                                  \
                 Ab + (size_t)_ar * K + _k0 + _ac * 8);                          \
            int _br = _idx >> 4, _bc = _idx & 15;                                \
            cp16(_bB + _br * BPAD_B + _bc * 16,                                  \
                 Bb + (size_t)(_k0 + _br) * N + _bc * 8);                        \
        }                                                                        \
        CP_COMMIT();                                                             \
    } while (0)

    LOAD_CHUNK(0, 0);

    for (int kt = 0; kt < ntiles; ++kt) {
        const int s = kt & 1;
        CP_WAIT(0);          // chunk kt landed (single group in flight)
        __syncthreads();     // warps done computing on stage s^1 (iter kt-1)
        if (kt + 1 < ntiles)
            LOAD_CHUNK(kt + 1, s ^ 1);   // overlaps compute below

        const uint32_t aS = smA_u + s * ASTG_B;
        const uint32_t bS = smB_u + s * BSTG_B;

        #pragma unroll
        for (int ks = 0; ks < 4; ++ks) {
            uint32_t a[4][4], bfr[4][2];
            #pragma unroll
            for (int mf = 0; mf < 4; ++mf) {
                uint32_t addr = aS
                    + (uint32_t)(wm + mf * 16 + (lane & 15)) * APAD_B
                    + (uint32_t)(ks * 16 + ((lane >> 4) << 3)) * 2;
                ldsm_x4(a[mf][0], a[mf][1], a[mf][2], a[mf][3], addr);
            }
            #pragma unroll
            for (int p = 0; p < 2; ++p) {
                uint32_t addr = bS
                    + (uint32_t)(ks * 16 + (lane & 15)) * BPAD_B
                    + (uint32_t)(wn + p * 16 + ((lane >> 4) << 3)) * 2;
                ldsm_x4t(bfr[2 * p][0], bfr[2 * p][1],
                         bfr[2 * p + 1][0], bfr[2 * p + 1][1], addr);
            }
            #pragma unroll
            for (int mf = 0; mf < 4; ++mf)
                #pragma unroll
                for (int nf = 0; nf < 4; ++nf)
                    MMA_F16(acc[mf][nf][0], acc[mf][nf][1],
                            acc[mf][nf][2], acc[mf][nf][3],
                            a[mf][0], a[mf][1], a[mf][2], a[mf][3],
                            bfr[nf][0], bfr[nf][1]);
        }
    }
    #undef LOAD_CHUNK

    #pragma unroll
    for (int mf = 0; mf < 4; ++mf) {
        const int row = m0 + wm + mf * 16 + g;
        #pragma unroll
        for (int nf = 0; nf < 4; ++nf) {
            const int col = n0 + wn + nf * 8 + 2 * t;
            float2 b2 = *reinterpret_cast<const float2*>(bias + col);
            float o00 = acc[mf][nf][0] + b2.x, o01 = acc[mf][nf][1] + b2.y;
            float o10 = acc[mf][nf][2] + b2.x, o11 = acc[mf][nf][3] + b2.y;
            if (sizeof(OutT) == 2) {
                __half* p0 = (__half*)C + (size_t)row * N + col;
                __half* p1 = (__half*)C + (size_t)(row + 8) * N + col;
                *reinterpret_cast<uint32_t*>(p0) = ph2(o00, o01);
                *reinterpret_cast<uint32_t*>(p1) = ph2(o10, o11);
            } else {
                float* p0 = (float*)C + (size_t)row * N + col;
                float* p1 = (float*)C + (size_t)(row + 8) * N + col;
                *reinterpret_cast<float2*>(p0) = make_float2(o00, o01);
                *reinterpret_cast<float2*>(p1) = make_float2(o10, o11);
            }
        }
    }
}

// ---------------------------------------------------------------------------
// f16 causal flash attention (exact R10 winner): cp.async double-buffered
// K/V, x4 ldmatrix. CTA: 128 threads / 4 warps; 64-query tile; 64-key tiles.
// ---------------------------------------------------------------------------
#define KSTH 72                      // halves per row (64 + 8 pad) -> 144 B
#define KROW_B (KSTH * 2)            // 144
#define KTILE_B (64 * KROW_B)        // 9216 per matrix
#define ASTAGE_B (2 * KTILE_B)       // K + V per stage: 18432
#define ASMEM (2 * ASTAGE_B)         // 36864

__global__ __launch_bounds__(128)
void attn_f16(__half* __restrict__ out)
{
    extern __shared__ __align__(16) char asmem[];
    const int b  = blockIdx.z;
    const int h  = blockIdx.y;
    const int qt = blockIdx.x;
    const int tid  = threadIdx.x;
    const int w    = tid >> 5;
    const int lane = tid & 31;
    const int g = lane >> 2;
    const int t = lane & 3;
    const int q0 = qt * 64;

    const size_t row3E = (size_t)3 * EMB;
    const __half* basep = g_qkvh + (size_t)b * SEQ * row3E;
    const uint32_t smu = s2u(asmem);

    // Q fragments (f16x2, pre-scaled by 1/8 — exact in f16)
    uint32_t qa[4][4];
    {
        const __half2 sc = __half2half2(__float2half_rn(0.125f));
        const __half* q0p = basep + (size_t)(q0 + w * 16 + g) * row3E + h * HDIM;
        const __half* q8p = q0p + 8 * row3E;
        #pragma unroll
        for (int ks = 0; ks < 4; ++ks) {
            __half2 v0 = *reinterpret_cast<const __half2*>(q0p + ks * 16 + 2 * t);
            __half2 v1 = *reinterpret_cast<const __half2*>(q8p + ks * 16 + 2 * t);
            __half2 v2 = *reinterpret_cast<const __half2*>(q0p + ks * 16 + 8 + 2 * t);
            __half2 v3 = *reinterpret_cast<const __half2*>(q8p + ks * 16 + 8 + 2 * t);
            v0 = __hmul2(v0, sc); v1 = __hmul2(v1, sc);
            v2 = __hmul2(v2, sc); v3 = __hmul2(v3, sc);
            qa[ks][0] = *reinterpret_cast<uint32_t*>(&v0);
            qa[ks][1] = *reinterpret_cast<uint32_t*>(&v1);
            qa[ks][2] = *reinterpret_cast<uint32_t*>(&v2);
            qa[ks][3] = *reinterpret_cast<uint32_t*>(&v3);
        }
    }

    float m0 = -INFINITY, m1 = -INFINITY, l0 = 0.f, l1 = 0.f;
    float o[8][4];
    #pragma unroll
    for (int nf = 0; nf < 8; ++nf)
        #pragma unroll
        for (int c = 0; c < 4; ++c) o[nf][c] = 0.f;

    #define LOAD_TILE(kt_, st_) do {                                             \
        const int _k0 = (kt_) * 64;                                              \
        const uint32_t _kB = smu + (st_) * ASTAGE_B;                             \
        const uint32_t _vB = _kB + KTILE_B;                                      \
        _Pragma("unroll")                                                        \
        for (int _i = 0; _i < 4; ++_i) {                                         \
            int _idx = tid + _i * 128;                                           \
            int _r = _idx >> 3;                                                  \
            int _cb = (_idx & 7) << 4;                                           \
            const __half* _rp = basep + (size_t)(_k0 + _r) * row3E + h * HDIM;   \
            cp16(_kB + _r * KROW_B + _cb, (const char*)(_rp + EMB) + _cb);       \
            cp16(_vB + _r * KROW_B + _cb, (const char*)(_rp + 2 * EMB) + _cb);   \
        }                                                                        \
        CP_COMMIT();                                                             \
    } while (0)

    const int ntile = q0 / 64 + 1;
    LOAD_TILE(0, 0);

    const int kq_row = lane & 7;
    const int kq_sel = (lane >> 4) & 1;
    const int kq_col = (lane >> 3) & 1;
    const int v_row = lane & 15;
    const int v_sel = (lane >> 4) & 1;

    for (int kt = 0; kt < ntile; ++kt) {
        const int st = kt & 1;
        if (kt + 1 < ntile) { CP_WAIT(1); } else { CP_WAIT(0); }
        __syncthreads();
        if (kt + 1 < ntile) LOAD_TILE(kt + 1, st ^ 1);

        const uint32_t kB = smu + st * ASTAGE_B;
        const uint32_t vB = kB + KTILE_B;

        float s[8][4];
        #pragma unroll
        for (int nf = 0; nf < 8; ++nf)
            #pragma unroll
            for (int c = 0; c < 4; ++c) s[nf][c] = 0.f;

        #pragma unroll
        for (int p = 0; p < 4; ++p) {
            uint32_t bf[2][2];
            #pragma unroll
            for (int ks = 0; ks < 4; ++ks) {
                uint32_t addr = kB
                    + (uint32_t)((2 * p + kq_sel) * 8 + kq_row) * KROW_B
                    + (uint32_t)(ks * 16 + kq_col * 8) * 2;
                ldsm_x4(bf[0][0], bf[0][1], bf[1][0], bf[1][1], addr);
                MMA_F16(s[2*p][0], s[2*p][1], s[2*p][2], s[2*p][3],
                        qa[ks][0], qa[ks][1], qa[ks][2], qa[ks][3],
                        bf[0][0], bf[0][1]);
                MMA_F16(s[2*p+1][0], s[2*p+1][1], s[2*p+1][2], s[2*p+1][3],
                        qa[ks][0], qa[ks][1], qa[ks][2], qa[ks][3],
                        bf[1][0], bf[1][1]);
            }
        }

        if (kt == ntile - 1) {
            const int r0l = w * 16 + g;
            #pragma unroll
            for (int nf = 0; nf < 8; ++nf) {
                const int c0 = nf * 8 + 2 * t;
                if (c0     > r0l)     s[nf][0] = -INFINITY;
                if (c0 + 1 > r0l)     s[nf][1] = -INFINITY;
                if (c0     > r0l + 8) s[nf][2] = -INFINITY;
                if (c0 + 1 > r0l + 8) s[nf][3] = -INFINITY;
            }
        }

        float tm0 = -INFINITY, tm1 = -INFINITY;
        #pragma unroll
        for (int nf = 0; nf < 8; ++nf) {
            tm0 = fmaxf(tm0, fmaxf(s[nf][0], s[nf][1]));
            tm1 = fmaxf(tm1, fmaxf(s[nf][2], s[nf][3]));
        }
        tm0 = fmaxf(tm0, __shfl_xor_sync(0xffffffffu, tm0, 1));
        tm0 = fmaxf(tm0, __shfl_xor_sync(0xffffffffu, tm0, 2));
        tm1 = fmaxf(tm1, __shfl_xor_sync(0xffffffffu, tm1, 1));
        tm1 = fmaxf(tm1, __shfl_xor_sync(0xffffffffu, tm1, 2));

        const float m0n = fmaxf(m0, tm0);
        const float m1n = fmaxf(m1, tm1);
        const float c0 = __expf(m0 - m0n);
        const float c1 = __expf(m1 - m1n);
        m0 = m0n; m1 = m1n;

        float ls0 = 0.f, ls1 = 0.f;
        #pragma unroll
        for (int nf = 0; nf < 8; ++nf) {
            s[nf][0] = __expf(s[nf][0] - m0n); ls0 += s[nf][0];
            s[nf][1] = __expf(s[nf][1] - m0n); ls0 += s[nf][1];
            s[nf][2] = __expf(s[nf][2] - m1n); ls1 += s[nf][2];
            s[nf][3] = __expf(s[nf][3] - m1n); ls1 += s[nf][3];
        }
        ls0 += __shfl_xor_sync(0xffffffffu, ls0, 1);
        ls0 += __shfl_xor_sync(0xffffffffu, ls0, 2);
        ls1 += __shfl_xor_sync(0xffffffffu, ls1, 1);
        ls1 += __shfl_xor_sync(0xffffffffu, ls1, 2);
        l0 = l0 * c0 + ls0;
        l1 = l1 * c1 + ls1;

        #pragma unroll
        for (int nf = 0; nf < 8; ++nf) {
            o[nf][0] *= c0; o[nf][1] *= c0;
            o[nf][2] *= c1; o[nf][3] *= c1;
        }

        uint32_t pa[4][4];
        #pragma unroll
        for (int ks = 0; ks < 4; ++ks) {
            pa[ks][0] = ph2(s[2 * ks][0],     s[2 * ks][1]);
            pa[ks][1] = ph2(s[2 * ks][2],     s[2 * ks][3]);
            pa[ks][2] = ph2(s[2 * ks + 1][0], s[2 * ks + 1][1]);
            pa[ks][3] = ph2(s[2 * ks + 1][2], s[2 * ks + 1][3]);
        }

        #pragma unroll
        for (int p = 0; p < 4; ++p) {
            #pragma unroll
            for (int ks = 0; ks < 4; ++ks) {
                uint32_t v0, v1, v2, v3;
                uint32_t addr = vB
                    + (uint32_t)(ks * 16 + v_row) * KROW_B
                    + (uint32_t)((2 * p + v_sel) * 8) * 2;
                ldsm_x4t(v0, v1, v2, v3, addr);
                MMA_F16(o[2*p][0], o[2*p][1], o[2*p][2], o[2*p][3],
                        pa[ks][0], pa[ks][1], pa[ks][2], pa[ks][3], v0, v1);
                MMA_F16(o[2*p+1][0], o[2*p+1][1], o[2*p+1][2], o[2*p+1][3],
                        pa[ks][0], pa[ks][1], pa[ks][2], pa[ks][3], v2, v3);
            }
        }
    }
    #undef LOAD_TILE

    const float inv0 = 1.f / l0;
    const float inv1 = 1.f / l1;
    const int gr0 = q0 + w * 16 + g;
    __half* op0 = out + ((size_t)b * SEQ + gr0) * EMB + h * HDIM;
    __half* op1 = op0 + 8 * EMB;
    #pragma unroll
    for (int nf = 0; nf < 8; ++nf) {
        const int col = nf * 8 + 2 * t;
        *reinterpret_cast<uint32_t*>(op0 + col) = ph2(o[nf][0] * inv0, o[nf][1] * inv0);
        *reinterpret_cast<uint32_t*>(op1 + col) = ph2(o[nf][2] * inv1, o[nf][3] * inv1);
    }
}

// ---------------------------------------------------------------------------
// Launch
// ---------------------------------------------------------------------------
extern "C" void kernel_launch(void* const* d_in, const int* in_sizes, int n_in,
                              void* d_out, int out_size)
{
    (void)in_sizes; (void)n_in; (void)out_size;
    const float* x     = (const float*)d_in[0];
    const float* W_qkv = (const float*)d_in[1];
    const float* b_qkv = (const float*)d_in[2];
    const float* W_o   = (const float*)d_in[3];
    const float* b_o   = (const float*)d_in[4];
    float* out = (float*)d_out;

    __half *xh = nullptr, *wqkvh = nullptr, *woh = nullptr;
    __half *qkvh = nullptr, *attnh = nullptr;
    cudaGetSymbolAddress((void**)&xh,    g_xh);
    cudaGetSymbolAddress((void**)&wqkvh, g_wqkvh);
    cudaGetSymbolAddress((void**)&woh,   g_woh);
    cudaGetSymbolAddress((void**)&qkvh,  g_qkvh);
    cudaGetSymbolAddress((void**)&attnh, g_attnh);

    cudaFuncSetAttribute(gemm_f16<__half>,
                         cudaFuncAttributeMaxDynamicSharedMemorySize, GSMEM);
    cudaFuncSetAttribute(gemm_f16<float>,
                         cudaFuncAttributeMaxDynamicSharedMemorySize, GSMEM);

    // 0) fused pre-pass conversion (x, W_qkv, W_o -> f16)
    prepass_cvt<<<(N4_ALL + 255) / 256, 256>>>(x, W_qkv, W_o);

    // 1) QKV projection (f16 out)
    gemm_f16<__half><<<dim3(3 * EMB / GBN, M_ROWS / GBM), 256, GSMEM>>>(
        xh, wqkvh, b_qkv, qkvh, M_ROWS, 3 * EMB, EMB);

    // 2) f16 causal flash attention (64-query CTAs, 4 warps — R10 winner)
    attn_f16<<<dim3(SEQ / 64, HEADS, BATCH), 128, ASMEM>>>(attnh);

    // 3) Output projection (f32 out)
    gemm_f16<float><<<dim3(EMB / GBN, M_ROWS / GBM), 256, GSMEM>>>(
        attnh, woh, b_o, out, M_ROWS, EMB, EMB);
}

// round 15
// speedup vs baseline: 1.0899x; 1.0021x over previous
#include <cuda_runtime.h>
#include <cuda_fp16.h>
#include <math.h>
#include <stdint.h>
#include <stddef.h>

// Problem constants
#define BATCH 4
#define SEQ   2048
#define EMB   1024
#define HEADS 16
#define HDIM  64
#define M_ROWS (BATCH*SEQ)   // 8192

// Scratch (device globals — allocation-free per harness rules)
__device__ __half g_xh[(size_t)M_ROWS * EMB];        // x f16
__device__ __half g_wqkvh[(size_t)EMB * 3 * EMB];    // W_qkv f16 [K,N]
__device__ __half g_woh[(size_t)EMB * EMB];          // W_o f16 [K,N]
__device__ __half g_qkvh[(size_t)M_ROWS * 3 * EMB];  // qkv f16
__device__ __half g_attnh[(size_t)M_ROWS * EMB];     // attention out f16

// ---------------------------------------------------------------------------
// Helpers
// ---------------------------------------------------------------------------
__device__ __forceinline__ uint32_t ph2(float a, float b) {
    __half2 h = __floats2half2_rn(a, b);
    return *reinterpret_cast<uint32_t*>(&h);
}
__device__ __forceinline__ uint32_t s2u(const void* p) {
    uint32_t r;
    asm("{ .reg .u64 t; cvta.to.shared.u64 t, %1; cvt.u32.u64 %0, t; }"
        : "=r"(r) : "l"(p));
    return r;
}

#define MMA_F16(d0,d1,d2,d3, a0,a1,a2,a3, b0,b1)                            \
    asm volatile(                                                           \
        "mma.sync.aligned.m16n8k16.row.col.f32.f16.f16.f32 "                \
        "{%0,%1,%2,%3}, {%4,%5,%6,%7}, {%8,%9}, {%0,%1,%2,%3};"             \
        : "+f"(d0), "+f"(d1), "+f"(d2), "+f"(d3)                            \
        : "r"(a0), "r"(a1), "r"(a2), "r"(a3), "r"(b0), "r"(b1))

__device__ __forceinline__ void ldsm_x4(uint32_t& r0, uint32_t& r1,
                                        uint32_t& r2, uint32_t& r3, uint32_t addr) {
    asm volatile("ldmatrix.sync.aligned.m8n8.x4.shared.b16 {%0,%1,%2,%3}, [%4];"
                 : "=r"(r0), "=r"(r1), "=r"(r2), "=r"(r3) : "r"(addr));
}
__device__ __forceinline__ void ldsm_x4t(uint32_t& r0, uint32_t& r1,
                                         uint32_t& r2, uint32_t& r3, uint32_t addr) {
    asm volatile("ldmatrix.sync.aligned.m8n8.x4.trans.shared.b16 {%0,%1,%2,%3}, [%4];"
                 : "=r"(r0), "=r"(r1), "=r"(r2), "=r"(r3) : "r"(addr));
}
__device__ __forceinline__ void cp16(uint32_t dst, const void* src) {
    asm volatile("cp.async.cg.shared.global [%0], [%1], 16;"
                 :: "r"(dst), "l"(src) : "memory");
}
#define CP_COMMIT() asm volatile("cp.async.commit_group;" ::: "memory")
#define CP_WAIT(n)  asm volatile("cp.async.wait_group %0;" :: "n"(n) : "memory")

// ---------------------------------------------------------------------------
// Fused pre-pass: convert x, W_qkv, W_o to f16 in one launch.
// ---------------------------------------------------------------------------
#define N4_X   (M_ROWS * EMB / 4)
#define N4_WQ  (3 * EMB * EMB / 4)
#define N4_WO  (EMB * EMB / 4)
#define N4_ALL (N4_X + N4_WQ + N4_WO)

__global__ __launch_bounds__(256)
void prepass_cvt(const float* __restrict__ x, const float* __restrict__ wq,
                 const float* __restrict__ wo)
{
    int i = blockIdx.x * 256 + threadIdx.x;
    const float* src;
    __half* dst;
    int j = i;
    if (j < N4_X)            { src = x;  dst = g_xh; }
    else if ((j -= N4_X) < N4_WQ)  { src = wq; dst = g_wqkvh; }
    else if ((j -= N4_WQ) < N4_WO) { src = wo; dst = g_woh; }
    else return;
    float4 v = reinterpret_cast<const float4*>(src)[j];
    uint2 o = make_uint2(ph2(v.x, v.y), ph2(v.z, v.w));
    reinterpret_cast<uint2*>(dst)[j] = o;
}

// ---------------------------------------------------------------------------
// f16 tensor-core GEMM (R14-proven): C = A[M,K] @ B[K,N] + bias
// CTA 128x128x64, 256 threads, warp tile 64x32, 2-stage cp.async, 1 barrier.
// ---------------------------------------------------------------------------
#define GBM 128
#define GBN 128
#define GBK 64
#define APAD_B 144
#define BPAD_B 272
#define ASTG_B (GBM * APAD_B)       // 18432 B
#define BSTG_B (GBK * BPAD_B)       // 17408 B
#define GSMEM (2 * (ASTG_B + BSTG_B))   // 71680 B

template <typename OutT>
__global__ __launch_bounds__(256)
void gemm_f16(const __half* __restrict__ A, const __half* __restrict__ B,
              const float* __restrict__ bias, OutT* __restrict__ C,
              int M, int N, int K)
{
    extern __shared__ __align__(16) char smem[];
    const int tid  = threadIdx.x;
    const int wid  = tid >> 5;
    const int lane = tid & 31;
    const int g = lane >> 2;
    const int t = lane & 3;
    const int wm = (wid >> 2) * 64;
    const int wn = (wid & 3) * 32;
    const int n0 = blockIdx.x * GBN;
    const int m0 = blockIdx.y * GBM;

    const uint32_t smA_u = s2u(smem);
    const uint32_t smB_u = smA_u + 2 * ASTG_B;

    const __half* Ab = A + (size_t)m0 * K;
    const __half* Bb = B + n0;

    float acc[4][4][4];
    #pragma unroll
    for (int i = 0; i < 4; ++i)
        #pragma unroll
        for (int j = 0; j < 4; ++j)
            #pragma unroll
            for (int c = 0; c < 4; ++c) acc[i][j][c] = 0.f;

    const int ntiles = K / GBK;

    #define LOAD_CHUNK(kc, st) do {                                              \
        const int _k0 = (kc) * GBK;                                              \
        const uint32_t _aB = smA_u + (st) * ASTG_B;                              \
        const uint32_t _bB = smB_u + (st) * BSTG_B;                              \
        _Pragma("unroll")                                                        \
        for (int _i = 0; _i < 4; ++_i) {                                         \
            int _idx = tid + _i * 256;                                           \
            int _ar = _idx >> 3, _ac = _idx & 7;                                 \
            cp16(_aB + _ar * APAD_B + _ac * 16,                                  \
                 Ab + (size_t)_ar * K + _k0 + _ac * 8);                          \
            int _br = _idx >> 4, _bc = _idx & 15;                                \
            cp16(_bB + _br * BPAD_B + _bc * 16,                                  \
                 Bb + (size_t)(_k0 + _br) * N + _bc * 8);                        \
        }                                                                        \
        CP_COMMIT();                                                             \
    } while (0)

    LOAD_CHUNK(0, 0);

    for (int kt = 0; kt < ntiles; ++kt) {
        const int s = kt & 1;
        CP_WAIT(0);
        __syncthreads();
        if (kt + 1 < ntiles)
            LOAD_CHUNK(kt + 1, s ^ 1);

        const uint32_t aS = smA_u + s * ASTG_B;
        const uint32_t bS = smB_u + s * BSTG_B;

        #pragma unroll
        for (int ks = 0; ks < 4; ++ks) {
            uint32_t a[4][4], bfr[4][2];
            #pragma unroll
            for (int mf = 0; mf < 4; ++mf) {
                uint32_t addr = aS
                    + (uint32_t)(wm + mf * 16 + (lane & 15)) * APAD_B
                    + (uint32_t)(ks * 16 + ((lane >> 4) << 3)) * 2;
                ldsm_x4(a[mf][0], a[mf][1], a[mf][2], a[mf][3], addr);
            }
            #pragma unroll
            for (int p = 0; p < 2; ++p) {
                uint32_t addr = bS
                    + (uint32_t)(ks * 16 + (lane & 15)) * BPAD_B
                    + (uint32_t)(wn + p * 16 + ((lane >> 4) << 3)) * 2;
                ldsm_x4t(bfr[2 * p][0], bfr[2 * p][1],
                         bfr[2 * p + 1][0], bfr[2 * p + 1][1], addr);
            }
            #pragma unroll
            for (int mf = 0; mf < 4; ++mf)
                #pragma unroll
                for (int nf = 0; nf < 4; ++nf)
                    MMA_F16(acc[mf][nf][0], acc[mf][nf][1],
                            acc[mf][nf][2], acc[mf][nf][3],
                            a[mf][0], a[mf][1], a[mf][2], a[mf][3],
                            bfr[nf][0], bfr[nf][1]);
        }
    }
    #undef LOAD_CHUNK

    #pragma unroll
    for (int mf = 0; mf < 4; ++mf) {
        const int row = m0 + wm + mf * 16 + g;
        #pragma unroll
        for (int nf = 0; nf < 4; ++nf) {
            const int col = n0 + wn + nf * 8 + 2 * t;
            float2 b2 = *reinterpret_cast<const float2*>(bias + col);
            float o00 = acc[mf][nf][0] + b2.x, o01 = acc[mf][nf][1] + b2.y;
            float o10 = acc[mf][nf][2] + b2.x, o11 = acc[mf][nf][3] + b2.y;
            if (sizeof(OutT) == 2) {
                __half* p0 = (__half*)C + (size_t)row * N + col;
                __half* p1 = (__half*)C + (size_t)(row + 8) * N + col;
                *reinterpret_cast<uint32_t*>(p0) = ph2(o00, o01);
                *reinterpret_cast<uint32_t*>(p1) = ph2(o10, o11);
            } else {
                float* p0 = (float*)C + (size_t)row * N + col;
                float* p1 = (float*)C + (size_t)(row + 8) * N + col;
                *reinterpret_cast<float2*>(p0) = make_float2(o00, o01);
                *reinterpret_cast<float2*>(p1) = make_float2(o10, o11);
            }
        }
    }
}

// ---------------------------------------------------------------------------
// f16 causal flash attention — 64-query CTA / 4 warps, 128-KEY tiles.
// Halves per-tile overhead (barriers, CP waits, softmax reductions) at the
// same MMA count per key. qt order reversed: longest CTAs scheduled first.
// ---------------------------------------------------------------------------
#define KSTH 72                      // halves per row (64 + 8 pad) -> 144 B
#define KROW_B (KSTH * 2)            // 144
#define KTILE_B (128 * KROW_B)       // 18432 per matrix (128 key rows)
#define ASTAGE_B (2 * KTILE_B)       // K + V per stage: 36864
#define ASMEM (2 * ASTAGE_B)         // 73728

__global__ __launch_bounds__(128)
void attn_f16(__half* __restrict__ out)
{
    extern __shared__ __align__(16) char asmem[];
    const int b  = blockIdx.z;
    const int h  = blockIdx.y;
    const int qt = gridDim.x - 1 - blockIdx.x;   // longest CTAs first
    const int tid  = threadIdx.x;
    const int w    = tid >> 5;
    const int lane = tid & 31;
    const int g = lane >> 2;
    const int t = lane & 3;
    const int q0 = qt * 64;

    const size_t row3E = (size_t)3 * EMB;
    const __half* basep = g_qkvh + (size_t)b * SEQ * row3E;
    const uint32_t smu = s2u(asmem);

    // Q fragments (f16x2, pre-scaled by 1/8 — exact in f16)
    uint32_t qa[4][4];
    {
        const __half2 sc = __half2half2(__float2half_rn(0.125f));
        const __half* q0p = basep + (size_t)(q0 + w * 16 + g) * row3E + h * HDIM;
        const __half* q8p = q0p + 8 * row3E;
        #pragma unroll
        for (int ks = 0; ks < 4; ++ks) {
            __half2 v0 = *reinterpret_cast<const __half2*>(q0p + ks * 16 + 2 * t);
            __half2 v1 = *reinterpret_cast<const __half2*>(q8p + ks * 16 + 2 * t);
            __half2 v2 = *reinterpret_cast<const __half2*>(q0p + ks * 16 + 8 + 2 * t);
            __half2 v3 = *reinterpret_cast<const __half2*>(q8p + ks * 16 + 8 + 2 * t);
            v0 = __hmul2(v0, sc); v1 = __hmul2(v1, sc);
            v2 = __hmul2(v2, sc); v3 = __hmul2(v3, sc);
            qa[ks][0] = *reinterpret_cast<uint32_t*>(&v0);
            qa[ks][1] = *reinterpret_cast<uint32_t*>(&v1);
            qa[ks][2] = *reinterpret_cast<uint32_t*>(&v2);
            qa[ks][3] = *reinterpret_cast<uint32_t*>(&v3);
        }
    }

    float m0 = -INFINITY, m1 = -INFINITY, l0 = 0.f, l1 = 0.f;
    float o[8][4];
    #pragma unroll
    for (int nf = 0; nf < 8; ++nf)
        #pragma unroll
        for (int c = 0; c < 4; ++c) o[nf][c] = 0.f;

    // 128-key tile loader: 128 rows x 128 B per matrix; 8 cp16/thread each
    #define LOAD_TILE(kt_, st_) do {                                             \
        const int _k0 = (kt_) * 128;                                             \
        const uint32_t _kB = smu + (st_) * ASTAGE_B;                             \
        const uint32_t _vB = _kB + KTILE_B;                                      \
        _Pragma("unroll")                                                        \
        for (int _i = 0; _i < 8; ++_i) {                                         \
            int _idx = tid + _i * 128;                                           \
            int _r = _idx >> 3;                                                  \
            int _cb = (_idx & 7) << 4;                                           \
            const __half* _rp = basep + (size_t)(_k0 + _r) * row3E + h * HDIM;   \
            cp16(_kB + _r * KROW_B + _cb, (const char*)(_rp + EMB) + _cb);       \
            cp16(_vB + _r * KROW_B + _cb, (const char*)(_rp + 2 * EMB) + _cb);   \
        }                                                                        \
        CP_COMMIT();                                                             \
    } while (0)

    const int ntile = (q0 + 64 + 127) / 128;   // last tile starts at or before q0
    LOAD_TILE(0, 0);

    const int kq_row = lane & 7;
    const int kq_sel = (lane >> 4) & 1;
    const int kq_col = (lane >> 3) & 1;
    const int v_row = lane & 15;
    const int v_sel = (lane >> 4) & 1;

    for (int kt = 0; kt < ntile; ++kt) {
        const int st = kt & 1;
        const int k0 = kt * 128;
        if (kt + 1 < ntile) { CP_WAIT(1); } else { CP_WAIT(0); }
        __syncthreads();
        if (kt + 1 < ntile) LOAD_TILE(kt + 1, st ^ 1);

        const uint32_t kB = smu + st * ASTAGE_B;
        const uint32_t vB = kB + KTILE_B;

        // Scores: S[16 x 128]
        float s[16][4];
        #pragma unroll
        for (int nf = 0; nf < 16; ++nf)
            #pragma unroll
            for (int c = 0; c < 4; ++c) s[nf][c] = 0.f;

        #pragma unroll
        for (int p = 0; p < 8; ++p) {
            uint32_t bf[2][2];
            #pragma unroll
            for (int ks = 0; ks < 4; ++ks) {
                uint32_t addr = kB
                    + (uint32_t)((2 * p + kq_sel) * 8 + kq_row) * KROW_B
                    + (uint32_t)(ks * 16 + kq_col * 8) * 2;
                ldsm_x4(bf[0][0], bf[0][1], bf[1][0], bf[1][1], addr);
                MMA_F16(s[2*p][0], s[2*p][1], s[2*p][2], s[2*p][3],
                        qa[ks][0], qa[ks][1], qa[ks][2], qa[ks][3],
                        bf[0][0], bf[0][1]);
                MMA_F16(s[2*p+1][0], s[2*p+1][1], s[2*p+1][2], s[2*p+1][3],
                        qa[ks][0], qa[ks][1], qa[ks][2], qa[ks][3],
                        bf[1][0], bf[1][1]);
            }
        }

        // Causal mask (any tile overlapping this warp's rows)
        if (k0 + 127 > q0 + w * 16) {
            const int r0g = q0 + w * 16 + g;
            #pragma unroll
            for (int nf = 0; nf < 16; ++nf) {
                const int cg = k0 + nf * 8 + 2 * t;
                if (cg     > r0g)     s[nf][0] = -INFINITY;
                if (cg + 1 > r0g)     s[nf][1] = -INFINITY;
                if (cg     > r0g + 8) s[nf][2] = -INFINITY;
                if (cg + 1 > r0g + 8) s[nf][3] = -INFINITY;
            }
        }

        // Online softmax over 128 keys
        float tm0 = -INFINITY, tm1 = -INFINITY;
        #pragma unroll
        for (int nf = 0; nf < 16; ++nf) {
            tm0 = fmaxf(tm0, fmaxf(s[nf][0], s[nf][1]));
            tm1 = fmaxf(tm1, fmaxf(s[nf][2], s[nf][3]));
        }
        tm0 = fmaxf(tm0, __shfl_xor_sync(0xffffffffu, tm0, 1));
        tm0 = fmaxf(tm0, __shfl_xor_sync(0xffffffffu, tm0, 2));
        tm1 = fmaxf(tm1, __shfl_xor_sync(0xffffffffu, tm1, 1));
        tm1 = fmaxf(tm1, __shfl_xor_sync(0xffffffffu, tm1, 2));

        const float m0n = fmaxf(m0, tm0);
        const float m1n = fmaxf(m1, tm1);
        const float c0 = __expf(m0 - m0n);
        const float c1 = __expf(m1 - m1n);
        m0 = m0n; m1 = m1n;

        float ls0 = 0.f, ls1 = 0.f;
        #pragma unroll
        for (int nf = 0; nf < 16; ++nf) {
            s[nf][0] = __expf(s[nf][0] - m0n); ls0 += s[nf][0];
            s[nf][1] = __expf(s[nf][1] - m0n); ls0 += s[nf][1];
            s[nf][2] = __expf(s[nf][2] - m1n); ls1 += s[nf][2];
            s[nf][3] = __expf(s[nf][3] - m1n); ls1 += s[nf][3];
        }
        ls0 += __shfl_xor_sync(0xffffffffu, ls0, 1);
        ls0 += __shfl_xor_sync(0xffffffffu, ls0, 2);
        ls1 += __shfl_xor_sync(0xffffffffu, ls1, 1);
        ls1 += __shfl_xor_sync(0xffffffffu, ls1, 2);
        l0 = l0 * c0 + ls0;
        l1 = l1 * c1 + ls1;

        #pragma unroll
        for (int nf = 0; nf < 8; ++nf) {
            o[nf][0] *= c0; o[nf][1] *= c0;
            o[nf][2] *= c1; o[nf][3] *= c1;
        }

        // P -> f16 A-fragments (8 k16 steps over 128 keys)
        uint32_t pa[8][4];
        #pragma unroll
        for (int ks = 0; ks < 8; ++ks) {
            pa[ks][0] = ph2(s[2 * ks][0],     s[2 * ks][1]);
            pa[ks][1] = ph2(s[2 * ks][2],     s[2 * ks][3]);
            pa[ks][2] = ph2(s[2 * ks + 1][0], s[2 * ks + 1][1]);
            pa[ks][3] = ph2(s[2 * ks + 1][2], s[2 * ks + 1][3]);
        }

        // O += P @ V
        #pragma unroll
        for (int p = 0; p < 4; ++p) {
            #pragma unroll
            for (int ks = 0; ks < 8; ++ks) {
                uint32_t v0, v1, v2, v3;
                uint32_t addr = vB
                    + (uint32_t)(ks * 16 + v_row) * KROW_B
                    + (uint32_t)((2 * p + v_sel) * 8) * 2;
                ldsm_x4t(v0, v1, v2, v3, addr);
                MMA_F16(o[2*p][0], o[2*p][1], o[2*p][2], o[2*p][3],
                        pa[ks][0], pa[ks][1], pa[ks][2], pa[ks][3], v0, v1);
                MMA_F16(o[2*p+1][0], o[2*p+1][1], o[2*p+1][2], o[2*p+1][3],
                        pa[ks][0], pa[ks][1], pa[ks][2], pa[ks][3], v2, v3);
            }
        }
    }
    #undef LOAD_TILE

    const float inv0 = 1.f / l0;
    const float inv1 = 1.f / l1;
    const int gr0 = q0 + w * 16 + g;
    __half* op0 = out + ((size_t)b * SEQ + gr0) * EMB + h * HDIM;
    __half* op1 = op0 + 8 * EMB;
    #pragma unroll
    for (int nf = 0; nf < 8; ++nf) {
        const int col = nf * 8 + 2 * t;
        *reinterpret_cast<uint32_t*>(op0 + col) = ph2(o[nf][0] * inv0, o[nf][1] * inv0);
        *reinterpret_cast<uint32_t*>(op1 + col) = ph2(o[nf][2] * inv1, o[nf][3] * inv1);
    }
}

// ---------------------------------------------------------------------------
// Launch
// ---------------------------------------------------------------------------
extern "C" void kernel_launch(void* const* d_in, const int* in_sizes, int n_in,
                              void* d_out, int out_size)
{
    (void)in_sizes; (void)n_in; (void)out_size;
    const float* x     = (const float*)d_in[0];
    const float* W_qkv = (const float*)d_in[1];
    const float* b_qkv = (const float*)d_in[2];
    const float* W_o   = (const float*)d_in[3];
    const float* b_o   = (const float*)d_in[4];
    float* out = (float*)d_out;

    __half *xh = nullptr, *wqkvh = nullptr, *woh = nullptr;
    __half *qkvh = nullptr, *attnh = nullptr;
    cudaGetSymbolAddress((void**)&xh,    g_xh);
    cudaGetSymbolAddress((void**)&wqkvh, g_wqkvh);
    cudaGetSymbolAddress((void**)&woh,   g_woh);
    cudaGetSymbolAddress((void**)&qkvh,  g_qkvh);
    cudaGetSymbolAddress((void**)&attnh, g_attnh);

    cudaFuncSetAttribute(gemm_f16<__half>,
                         cudaFuncAttributeMaxDynamicSharedMemorySize, GSMEM);
    cudaFuncSetAttribute(gemm_f16<float>,
                         cudaFuncAttributeMaxDynamicSharedMemorySize, GSMEM);
    cudaFuncSetAttribute(attn_f16,
                         cudaFuncAttributeMaxDynamicSharedMemorySize, ASMEM);

    // 0) fused pre-pass conversion (x, W_qkv, W_o -> f16)
    prepass_cvt<<<(N4_ALL + 255) / 256, 256>>>(x, W_qkv, W_o);

    // 1) QKV projection (f16 out)
    gemm_f16<__half><<<dim3(3 * EMB / GBN, M_ROWS / GBM), 256, GSMEM>>>(
        xh, wqkvh, b_qkv, qkvh, M_ROWS, 3 * EMB, EMB);

    // 2) f16 causal flash attention (64-query CTAs, 128-key tiles)
    attn_f16<<<dim3(SEQ / 64, HEADS, BATCH), 128, ASMEM>>>(attnh);

    // 3) Output projection (f32 out)
    gemm_f16<float><<<dim3(EMB / GBN, M_ROWS / GBM), 256, GSMEM>>>(
        attnh, woh, b_o, out, M_ROWS, EMB, EMB);
}

// round 16
// speedup vs baseline: 1.1052x; 1.0140x over previous
#include <cuda_runtime.h>
#include <cuda_fp16.h>
#include <math.h>
#include <stdint.h>
#include <stddef.h>

// Problem constants
#define BATCH 4
#define SEQ   2048
#define EMB   1024
#define HEADS 16
#define HDIM  64
#define M_ROWS (BATCH*SEQ)   // 8192
#define NQT   (SEQ / 64)     // 32 query tiles per (b,h)

// Scratch (device globals — allocation-free per harness rules)
__device__ __half g_xh[(size_t)M_ROWS * EMB];        // x f16
__device__ __half g_wqkvh[(size_t)EMB * 3 * EMB];    // W_qkv f16 [K,N]
__device__ __half g_woh[(size_t)EMB * EMB];          // W_o f16 [K,N]
__device__ __half g_qkvh[(size_t)M_ROWS * 3 * EMB];  // qkv f16
__device__ __half g_attnh[(size_t)M_ROWS * EMB];     // attention out f16

// ---------------------------------------------------------------------------
// Helpers
// ---------------------------------------------------------------------------
__device__ __forceinline__ uint32_t ph2(float a, float b) {
    __half2 h = __floats2half2_rn(a, b);
    return *reinterpret_cast<uint32_t*>(&h);
}
__device__ __forceinline__ uint32_t s2u(const void* p) {
    uint32_t r;
    asm("{ .reg .u64 t; cvta.to.shared.u64 t, %1; cvt.u32.u64 %0, t; }"
        : "=r"(r) : "l"(p));
    return r;
}

#define MMA_F16(d0,d1,d2,d3, a0,a1,a2,a3, b0,b1)                            \
    asm volatile(                                                           \
        "mma.sync.aligned.m16n8k16.row.col.f32.f16.f16.f32 "                \
        "{%0,%1,%2,%3}, {%4,%5,%6,%7}, {%8,%9}, {%0,%1,%2,%3};"             \
        : "+f"(d0), "+f"(d1), "+f"(d2), "+f"(d3)                            \
        : "r"(a0), "r"(a1), "r"(a2), "r"(a3), "r"(b0), "r"(b1))

__device__ __forceinline__ void ldsm_x4(uint32_t& r0, uint32_t& r1,
                                        uint32_t& r2, uint32_t& r3, uint32_t addr) {
    asm volatile("ldmatrix.sync.aligned.m8n8.x4.shared.b16 {%0,%1,%2,%3}, [%4];"
                 : "=r"(r0), "=r"(r1), "=r"(r2), "=r"(r3) : "r"(addr));
}
__device__ __forceinline__ void ldsm_x4t(uint32_t& r0, uint32_t& r1,
                                         uint32_t& r2, uint32_t& r3, uint32_t addr) {
    asm volatile("ldmatrix.sync.aligned.m8n8.x4.trans.shared.b16 {%0,%1,%2,%3}, [%4];"
                 : "=r"(r0), "=r"(r1), "=r"(r2), "=r"(r3) : "r"(addr));
}
__device__ __forceinline__ void cp16(uint32_t dst, const void* src) {
    asm volatile("cp.async.cg.shared.global [%0], [%1], 16;"
                 :: "r"(dst), "l"(src) : "memory");
}
#define CP_COMMIT() asm volatile("cp.async.commit_group;" ::: "memory")
#define CP_WAIT(n)  asm volatile("cp.async.wait_group %0;" :: "n"(n) : "memory")

// ---------------------------------------------------------------------------
// Fused pre-pass: convert x, W_qkv, W_o to f16 in one launch.
// ---------------------------------------------------------------------------
#define N4_X   (M_ROWS * EMB / 4)
#define N4_WQ  (3 * EMB * EMB / 4)
#define N4_WO  (EMB * EMB / 4)
#define N4_ALL (N4_X + N4_WQ + N4_WO)

__global__ __launch_bounds__(256)
void prepass_cvt(const float* __restrict__ x, const float* __restrict__ wq,
                 const float* __restrict__ wo)
{
    int i = blockIdx.x * 256 + threadIdx.x;
    const float* src;
    __half* dst;
    int j = i;
    if (j < N4_X)            { src = x;  dst = g_xh; }
    else if ((j -= N4_X) < N4_WQ)  { src = wq; dst = g_wqkvh; }
    else if ((j -= N4_WQ) < N4_WO) { src = wo; dst = g_woh; }
    else return;
    float4 v = reinterpret_cast<const float4*>(src)[j];
    uint2 o = make_uint2(ph2(v.x, v.y), ph2(v.z, v.w));
    reinterpret_cast<uint2*>(dst)[j] = o;
}

// ---------------------------------------------------------------------------
// f16 tensor-core GEMM (R14-proven): C = A[M,K] @ B[K,N] + bias
// CTA 128x128x64, 256 threads, warp tile 64x32, 2-stage cp.async, 1 barrier.
// ---------------------------------------------------------------------------
#define GBM 128
#define GBN 128
#define GBK 64
#define APAD_B 144
#define BPAD_B 272
#define ASTG_B (GBM * APAD_B)       // 18432 B
#define BSTG_B (GBK * BPAD_B)       // 17408 B
#define GSMEM (2 * (ASTG_B + BSTG_B))   // 71680 B

template <typename OutT>
__global__ __launch_bounds__(256)
void gemm_f16(const __half* __restrict__ A, const __half* __restrict__ B,
              const float* __restrict__ bias, OutT* __restrict__ C,
              int M, int N, int K)
{
    extern __shared__ __align__(16) char smem[];
    const int tid  = threadIdx.x;
    const int wid  = tid >> 5;
    const int lane = tid & 31;
    const int g = lane >> 2;
    const int t = lane & 3;
    const int wm = (wid >> 2) * 64;
    const int wn = (wid & 3) * 32;
    const int n0 = blockIdx.x * GBN;
    const int m0 = blockIdx.y * GBM;

    const uint32_t smA_u = s2u(smem);
    const uint32_t smB_u = smA_u + 2 * ASTG_B;

    const __half* Ab = A + (size_t)m0 * K;
    const __half* Bb = B + n0;

    float acc[4][4][4];
    #pragma unroll
    for (int i = 0; i < 4; ++i)
        #pragma unroll
        for (int j = 0; j < 4; ++j)
            #pragma unroll
            for (int c = 0; c < 4; ++c) acc[i][j][c] = 0.f;

    const int ntiles = K / GBK;

    #define LOAD_CHUNK(kc, st) do {                                              \
        const int _k0 = (kc) * GBK;                                              \
        const uint32_t _aB = smA_u + (st) * ASTG_B;                              \
        const uint32_t _bB = smB_u + (st) * BSTG_B;                              \
        _Pragma("unroll")                                                        \
        for (int _i = 0; _i < 4; ++_i) {                                         \
            int _idx = tid + _i * 256;                                           \
            int _ar = _idx >> 3, _ac = _idx & 7;                                 \
            cp16(_aB + _ar * APAD_B + _ac * 16,                                  \
                 Ab + (size_t)_ar * K + _k0 + _ac * 8);                          \
            int _br = _idx >> 4, _bc = _idx & 15;                                \
            cp16(_bB + _br * BPAD_B + _bc * 16,                                  \
                 Bb + (size_t)(_k0 + _br) * N + _bc * 8);                        \
        }                                                                        \
        CP_COMMIT();                                                             \
    } while (0)

    LOAD_CHUNK(0, 0);

    for (int kt = 0; kt < ntiles; ++kt) {
        const int s = kt & 1;
        CP_WAIT(0);
        __syncthreads();
        if (kt + 1 < ntiles)
            LOAD_CHUNK(kt + 1, s ^ 1);

        const uint32_t aS = smA_u + s * ASTG_B;
        const uint32_t bS = smB_u + s * BSTG_B;

        #pragma unroll
        for (int ks = 0; ks < 4; ++ks) {
            uint32_t a[4][4], bfr[4][2];
            #pragma unroll
            for (int mf = 0; mf < 4; ++mf) {
                uint32_t addr = aS
                    + (uint32_t)(wm + mf * 16 + (lane & 15)) * APAD_B
                    + (uint32_t)(ks * 16 + ((lane >> 4) << 3)) * 2;
                ldsm_x4(a[mf][0], a[mf][1], a[mf][2], a[mf][3], addr);
            }
            #pragma unroll
            for (int p = 0; p < 2; ++p) {
                uint32_t addr = bS
                    + (uint32_t)(ks * 16 + (lane & 15)) * BPAD_B
                    + (uint32_t)(wn + p * 16 + ((lane >> 4) << 3)) * 2;
                ldsm_x4t(bfr[2 * p][0], bfr[2 * p][1],
                         bfr[2 * p + 1][0], bfr[2 * p + 1][1], addr);
            }
            #pragma unroll
            for (int mf = 0; mf < 4; ++mf)
                #pragma unroll
                for (int nf = 0; nf < 4; ++nf)
                    MMA_F16(acc[mf][nf][0], acc[mf][nf][1],
                            acc[mf][nf][2], acc[mf][nf][3],
                            a[mf][0], a[mf][1], a[mf][2], a[mf][3],
                            bfr[nf][0], bfr[nf][1]);
        }
    }
    #undef LOAD_CHUNK

    #pragma unroll
    for (int mf = 0; mf < 4; ++mf) {
        const int row = m0 + wm + mf * 16 + g;
        #pragma unroll
        for (int nf = 0; nf < 4; ++nf) {
            const int col = n0 + wn + nf * 8 + 2 * t;
            float2 b2 = *reinterpret_cast<const float2*>(bias + col);
            float o00 = acc[mf][nf][0] + b2.x, o01 = acc[mf][nf][1] + b2.y;
            float o10 = acc[mf][nf][2] + b2.x, o11 = acc[mf][nf][3] + b2.y;
            if (sizeof(OutT) == 2) {
                __half* p0 = (__half*)C + (size_t)row * N + col;
                __half* p1 = (__half*)C + (size_t)(row + 8) * N + col;
                *reinterpret_cast<uint32_t*>(p0) = ph2(o00, o01);
                *reinterpret_cast<uint32_t*>(p1) = ph2(o10, o11);
            } else {
                float* p0 = (float*)C + (size_t)row * N + col;
                float* p1 = (float*)C + (size_t)(row + 8) * N + col;
                *reinterpret_cast<float2*>(p0) = make_float2(o00, o01);
                *reinterpret_cast<float2*>(p1) = make_float2(o10, o11);
            }
        }
    }
}

// ---------------------------------------------------------------------------
// f16 causal flash attention — work-balanced: each CTA processes TWO query
// tiles, qt and NQT-1-qt, so per-CTA key work is uniform (33 x 64 keys).
// Per-q-tile body identical to R15: 4 warps, 128-key double-buffered tiles.
// ---------------------------------------------------------------------------
#define KSTH 72                      // halves per row (64 + 8 pad) -> 144 B
#define KROW_B (KSTH * 2)            // 144
#define KTILE_B (128 * KROW_B)       // 18432 per matrix (128 key rows)
#define ASTAGE_B (2 * KTILE_B)       // K + V per stage: 36864
#define ASMEM (2 * ASTAGE_B)         // 73728

__global__ __launch_bounds__(128)
void attn_f16(__half* __restrict__ out)
{
    extern __shared__ __align__(16) char asmem[];
    const int b  = blockIdx.z;
    const int h  = blockIdx.y;
    const int tid  = threadIdx.x;
    const int w    = tid >> 5;
    const int lane = tid & 31;
    const int g = lane >> 2;
    const int t = lane & 3;

    const size_t row3E = (size_t)3 * EMB;
    const __half* basep = g_qkvh + (size_t)b * SEQ * row3E;
    const uint32_t smu = s2u(asmem);

    const int kq_row = lane & 7;
    const int kq_sel = (lane >> 4) & 1;
    const int kq_col = (lane >> 3) & 1;
    const int v_row = lane & 15;
    const int v_sel = (lane >> 4) & 1;

    #define LOAD_TILE(kt_, st_) do {                                             \
        const int _k0 = (kt_) * 128;                                             \
        const uint32_t _kB = smu + (st_) * ASTAGE_B;                             \
        const uint32_t _vB = _kB + KTILE_B;                                      \
        _Pragma("unroll")                                                        \
        for (int _i = 0; _i < 8; ++_i) {                                         \
            int _idx = tid + _i * 128;                                           \
            int _r = _idx >> 3;                                                  \
            int _cb = (_idx & 7) << 4;                                           \
            const __half* _rp = basep + (size_t)(_k0 + _r) * row3E + h * HDIM;   \
            cp16(_kB + _r * KROW_B + _cb, (const char*)(_rp + EMB) + _cb);       \
            cp16(_vB + _r * KROW_B + _cb, (const char*)(_rp + 2 * EMB) + _cb);   \
        }                                                                        \
        CP_COMMIT();                                                             \
    } while (0)

    // Two query tiles per CTA: hi first (more work to overlap), then lo.
    #pragma unroll 1
    for (int half = 0; half < 2; ++half) {
        const int qt = half == 0 ? (NQT - 1 - blockIdx.x) : blockIdx.x;
        const int q0 = qt * 64;

        // Q fragments (f16x2, pre-scaled by 1/8 — exact in f16)
        uint32_t qa[4][4];
        {
            const __half2 sc = __half2half2(__float2half_rn(0.125f));
            const __half* q0p = basep + (size_t)(q0 + w * 16 + g) * row3E + h * HDIM;
            const __half* q8p = q0p + 8 * row3E;
            #pragma unroll
            for (int ks = 0; ks < 4; ++ks) {
                __half2 v0 = *reinterpret_cast<const __half2*>(q0p + ks * 16 + 2 * t);
                __half2 v1 = *reinterpret_cast<const __half2*>(q8p + ks * 16 + 2 * t);
                __half2 v2 = *reinterpret_cast<const __half2*>(q0p + ks * 16 + 8 + 2 * t);
                __half2 v3 = *reinterpret_cast<const __half2*>(q8p + ks * 16 + 8 + 2 * t);
                v0 = __hmul2(v0, sc); v1 = __hmul2(v1, sc);
                v2 = __hmul2(v2, sc); v3 = __hmul2(v3, sc);
                qa[ks][0] = *reinterpret_cast<uint32_t*>(&v0);
                qa[ks][1] = *reinterpret_cast<uint32_t*>(&v1);
                qa[ks][2] = *reinterpret_cast<uint32_t*>(&v2);
                qa[ks][3] = *reinterpret_cast<uint32_t*>(&v3);
            }
        }

        float m0 = -INFINITY, m1 = -INFINITY, l0 = 0.f, l1 = 0.f;
        float o[8][4];
        #pragma unroll
        for (int nf = 0; nf < 8; ++nf)
            #pragma unroll
            for (int c = 0; c < 4; ++c) o[nf][c] = 0.f;

        const int ntile = (q0 + 64 + 127) / 128;

        __syncthreads();   // protect smem stage reuse across halves
        LOAD_TILE(0, 0);

        for (int kt = 0; kt < ntile; ++kt) {
            const int st = kt & 1;
            const int k0 = kt * 128;
            if (kt + 1 < ntile) { CP_WAIT(1); } else { CP_WAIT(0); }
            __syncthreads();
            if (kt + 1 < ntile) LOAD_TILE(kt + 1, st ^ 1);

            const uint32_t kB = smu + st * ASTAGE_B;
            const uint32_t vB = kB + KTILE_B;

            // Scores: S[16 x 128]
            float s[16][4];
            #pragma unroll
            for (int nf = 0; nf < 16; ++nf)
                #pragma unroll
                for (int c = 0; c < 4; ++c) s[nf][c] = 0.f;

            #pragma unroll
            for (int p = 0; p < 8; ++p) {
                uint32_t bf[2][2];
                #pragma unroll
                for (int ks = 0; ks < 4; ++ks) {
                    uint32_t addr = kB
                        + (uint32_t)((2 * p + kq_sel) * 8 + kq_row) * KROW_B
                        + (uint32_t)(ks * 16 + kq_col * 8) * 2;
                    ldsm_x4(bf[0][0], bf[0][1], bf[1][0], bf[1][1], addr);
                    MMA_F16(s[2*p][0], s[2*p][1], s[2*p][2], s[2*p][3],
                            qa[ks][0], qa[ks][1], qa[ks][2], qa[ks][3],
                            bf[0][0], bf[0][1]);
                    MMA_F16(s[2*p+1][0], s[2*p+1][1], s[2*p+1][2], s[2*p+1][3],
                            qa[ks][0], qa[ks][1], qa[ks][2], qa[ks][3],
                            bf[1][0], bf[1][1]);
                }
            }

            // Causal mask
            if (k0 + 127 > q0 + w * 16) {
                const int r0g = q0 + w * 16 + g;
                #pragma unroll
                for (int nf = 0; nf < 16; ++nf) {
                    const int cg = k0 + nf * 8 + 2 * t;
                    if (cg     > r0g)     s[nf][0] = -INFINITY;
                    if (cg + 1 > r0g)     s[nf][1] = -INFINITY;
                    if (cg     > r0g + 8) s[nf][2] = -INFINITY;
                    if (cg + 1 > r0g + 8) s[nf][3] = -INFINITY;
                }
            }

            // Online softmax over 128 keys
            float tm0 = -INFINITY, tm1 = -INFINITY;
            #pragma unroll
            for (int nf = 0; nf < 16; ++nf) {
                tm0 = fmaxf(tm0, fmaxf(s[nf][0], s[nf][1]));
                tm1 = fmaxf(tm1, fmaxf(s[nf][2], s[nf][3]));
            }
            tm0 = fmaxf(tm0, __shfl_xor_sync(0xffffffffu, tm0, 1));
            tm0 = fmaxf(tm0, __shfl_xor_sync(0xffffffffu, tm0, 2));
            tm1 = fmaxf(tm1, __shfl_xor_sync(0xffffffffu, tm1, 1));
            tm1 = fmaxf(tm1, __shfl_xor_sync(0xffffffffu, tm1, 2));

            const float m0n = fmaxf(m0, tm0);
            const float m1n = fmaxf(m1, tm1);
            const float c0 = __expf(m0 - m0n);
            const float c1 = __expf(m1 - m1n);
            m0 = m0n; m1 = m1n;

            float ls0 = 0.f, ls1 = 0.f;
            #pragma unroll
            for (int nf = 0; nf < 16; ++nf) {
                s[nf][0] = __expf(s[nf][0] - m0n); ls0 += s[nf][0];
                s[nf][1] = __expf(s[nf][1] - m0n); ls0 += s[nf][1];
                s[nf][2] = __expf(s[nf][2] - m1n); ls1 += s[nf][2];
                s[nf][3] = __expf(s[nf][3] - m1n); ls1 += s[nf][3];
            }
            ls0 += __shfl_xor_sync(0xffffffffu, ls0, 1);
            ls0 += __shfl_xor_sync(0xffffffffu, ls0, 2);
            ls1 += __shfl_xor_sync(0xffffffffu, ls1, 1);
            ls1 += __shfl_xor_sync(0xffffffffu, ls1, 2);
            l0 = l0 * c0 + ls0;
            l1 = l1 * c1 + ls1;

            #pragma unroll
            for (int nf = 0; nf < 8; ++nf) {
                o[nf][0] *= c0; o[nf][1] *= c0;
                o[nf][2] *= c1; o[nf][3] *= c1;
            }

            uint32_t pa[8][4];
            #pragma unroll
            for (int ks = 0; ks < 8; ++ks) {
                pa[ks][0] = ph2(s[2 * ks][0],     s[2 * ks][1]);
                pa[ks][1] = ph2(s[2 * ks][2],     s[2 * ks][3]);
                pa[ks][2] = ph2(s[2 * ks + 1][0], s[2 * ks + 1][1]);
                pa[ks][3] = ph2(s[2 * ks + 1][2], s[2 * ks + 1][3]);
            }

            #pragma unroll
            for (int p = 0; p < 4; ++p) {
                #pragma unroll
                for (int ks = 0; ks < 8; ++ks) {
                    uint32_t v0, v1, v2, v3;
                    uint32_t addr = vB
                        + (uint32_t)(ks * 16 + v_row) * KROW_B
                        + (uint32_t)((2 * p + v_sel) * 8) * 2;
                    ldsm_x4t(v0, v1, v2, v3, addr);
                    MMA_F16(o[2*p][0], o[2*p][1], o[2*p][2], o[2*p][3],
                            pa[ks][0], pa[ks][1], pa[ks][2], pa[ks][3], v0, v1);
                    MMA_F16(o[2*p+1][0], o[2*p+1][1], o[2*p+1][2], o[2*p+1][3],
                            pa[ks][0], pa[ks][1], pa[ks][2], pa[ks][3], v2, v3);
                }
            }
        }

        // Epilogue -> f16
        const float inv0 = 1.f / l0;
        const float inv1 = 1.f / l1;
        const int gr0 = q0 + w * 16 + g;
        __half* op0 = out + ((size_t)b * SEQ + gr0) * EMB + h * HDIM;
        __half* op1 = op0 + 8 * EMB;
        #pragma unroll
        for (int nf = 0; nf < 8; ++nf) {
            const int col = nf * 8 + 2 * t;
            *reinterpret_cast<uint32_t*>(op0 + col) =
                ph2(o[nf][0] * inv0, o[nf][1] * inv0);
            *reinterpret_cast<uint32_t*>(op1 + col) =
                ph2(o[nf][2] * inv1, o[nf][3] * inv1);
        }
    }
    #undef LOAD_TILE
}

// ---------------------------------------------------------------------------
// Launch
// ---------------------------------------------------------------------------
extern "C" void kernel_launch(void* const* d_in, const int* in_sizes, int n_in,
                              void* d_out, int out_size)
{
    (void)in_sizes; (void)n_in; (void)out_size;
    const float* x     = (const float*)d_in[0];
    const float* W_qkv = (const float*)d_in[1];
    const float* b_qkv = (const float*)d_in[2];
    const float* W_o   = (const float*)d_in[3];
    const float* b_o   = (const float*)d_in[4];
    float* out = (float*)d_out;

    __half *xh = nullptr, *wqkvh = nullptr, *woh = nullptr;
    __half *qkvh = nullptr, *attnh = nullptr;
    cudaGetSymbolAddress((void**)&xh,    g_xh);
    cudaGetSymbolAddress((void**)&wqkvh, g_wqkvh);
    cudaGetSymbolAddress((void**)&woh,   g_woh);
    cudaGetSymbolAddress((void**)&qkvh,  g_qkvh);
    cudaGetSymbolAddress((void**)&attnh, g_attnh);

    cudaFuncSetAttribute(gemm_f16<__half>,
                         cudaFuncAttributeMaxDynamicSharedMemorySize, GSMEM);
    cudaFuncSetAttribute(gemm_f16<float>,
                         cudaFuncAttributeMaxDynamicSharedMemorySize, GSMEM);
    cudaFuncSetAttribute(attn_f16,
                         cudaFuncAttributeMaxDynamicSharedMemorySize, ASMEM);

    // 0) fused pre-pass conversion (x, W_qkv, W_o -> f16)
    prepass_cvt<<<(N4_ALL + 255) / 256, 256>>>(x, W_qkv, W_o);

    // 1) QKV projection (f16 out)
    gemm_f16<__half><<<dim3(3 * EMB / GBN, M_ROWS / GBM), 256, GSMEM>>>(
        xh, wqkvh, b_qkv, qkvh, M_ROWS, 3 * EMB, EMB);

    // 2) f16 causal flash attention (paired query tiles — uniform CTA work)
    attn_f16<<<dim3(NQT / 2, HEADS, BATCH), 128, ASMEM>>>(attnh);

    // 3) Output projection (f32 out)
    gemm_f16<float><<<dim3(EMB / GBN, M_ROWS / GBM), 256, GSMEM>>>(
        attnh, woh, b_o, out, M_ROWS, EMB, EMB);
}

// round 17
// speedup vs baseline: 1.1177x; 1.0113x over previous
#include <cuda_runtime.h>
#include <cuda_fp16.h>
#include <math.h>
#include <stdint.h>
#include <stddef.h>

// Problem constants
#define BATCH 4
#define SEQ   2048
#define EMB   1024
#define HEADS 16
#define HDIM  64
#define M_ROWS (BATCH*SEQ)   // 8192
#define NQT   (SEQ / 64)     // 32 query tiles per (b,h)
#define NWORK (BATCH * HEADS * NQT)   // 2048 work items
#define NPERS 444                     // persistent CTAs (148 SMs x 3)

// Scratch (device globals — allocation-free per harness rules)
__device__ __half g_xh[(size_t)M_ROWS * EMB];
__device__ __half g_wqkvh[(size_t)EMB * 3 * EMB];
__device__ __half g_woh[(size_t)EMB * EMB];
__device__ __half g_qkvh[(size_t)M_ROWS * 3 * EMB];
__device__ __half g_attnh[(size_t)M_ROWS * EMB];
__device__ int    g_ctr;             // dynamic work counter

// ---------------------------------------------------------------------------
// Helpers
// ---------------------------------------------------------------------------
__device__ __forceinline__ uint32_t ph2(float a, float b) {
    __half2 h = __floats2half2_rn(a, b);
    return *reinterpret_cast<uint32_t*>(&h);
}
__device__ __forceinline__ uint32_t s2u(const void* p) {
    uint32_t r;
    asm("{ .reg .u64 t; cvta.to.shared.u64 t, %1; cvt.u32.u64 %0, t; }"
        : "=r"(r) : "l"(p));
    return r;
}

#define MMA_F16(d0,d1,d2,d3, a0,a1,a2,a3, b0,b1)                            \
    asm volatile(                                                           \
        "mma.sync.aligned.m16n8k16.row.col.f32.f16.f16.f32 "                \
        "{%0,%1,%2,%3}, {%4,%5,%6,%7}, {%8,%9}, {%0,%1,%2,%3};"             \
        : "+f"(d0), "+f"(d1), "+f"(d2), "+f"(d3)                            \
        : "r"(a0), "r"(a1), "r"(a2), "r"(a3), "r"(b0), "r"(b1))

__device__ __forceinline__ void ldsm_x4(uint32_t& r0, uint32_t& r1,
                                        uint32_t& r2, uint32_t& r3, uint32_t addr) {
    asm volatile("ldmatrix.sync.aligned.m8n8.x4.shared.b16 {%0,%1,%2,%3}, [%4];"
                 : "=r"(r0), "=r"(r1), "=r"(r2), "=r"(r3) : "r"(addr));
}
__device__ __forceinline__ void ldsm_x4t(uint32_t& r0, uint32_t& r1,
                                         uint32_t& r2, uint32_t& r3, uint32_t addr) {
    asm volatile("ldmatrix.sync.aligned.m8n8.x4.trans.shared.b16 {%0,%1,%2,%3}, [%4];"
                 : "=r"(r0), "=r"(r1), "=r"(r2), "=r"(r3) : "r"(addr));
}
__device__ __forceinline__ void cp16(uint32_t dst, const void* src) {
    asm volatile("cp.async.cg.shared.global [%0], [%1], 16;"
                 :: "r"(dst), "l"(src) : "memory");
}
#define CP_COMMIT() asm volatile("cp.async.commit_group;" ::: "memory")
#define CP_WAIT(n)  asm volatile("cp.async.wait_group %0;" :: "n"(n) : "memory")

// ---------------------------------------------------------------------------
// Fused pre-pass: convert x, W_qkv, W_o to f16 + reset work counter.
// ---------------------------------------------------------------------------
#define N4_X   (M_ROWS * EMB / 4)
#define N4_WQ  (3 * EMB * EMB / 4)
#define N4_WO  (EMB * EMB / 4)
#define N4_ALL (N4_X + N4_WQ + N4_WO)

__global__ __launch_bounds__(256)
void prepass_cvt(const float* __restrict__ x, const float* __restrict__ wq,
                 const float* __restrict__ wo)
{
    int i = blockIdx.x * 256 + threadIdx.x;
    if (i == 0) g_ctr = 0;
    const float* src;
    __half* dst;
    int j = i;
    if (j < N4_X)            { src = x;  dst = g_xh; }
    else if ((j -= N4_X) < N4_WQ)  { src = wq; dst = g_wqkvh; }
    else if ((j -= N4_WQ) < N4_WO) { src = wo; dst = g_woh; }
    else return;
    float4 v = reinterpret_cast<const float4*>(src)[j];
    uint2 o = make_uint2(ph2(v.x, v.y), ph2(v.z, v.w));
    reinterpret_cast<uint2*>(dst)[j] = o;
}

// ---------------------------------------------------------------------------
// f16 tensor-core GEMM (R14-proven): C = A[M,K] @ B[K,N] + bias
// CTA 128x128x64, 256 threads, warp tile 64x32, 2-stage cp.async, 1 barrier.
// ---------------------------------------------------------------------------
#define GBM 128
#define GBN 128
#define GBK 64
#define APAD_B 144
#define BPAD_B 272
#define ASTG_B (GBM * APAD_B)
#define BSTG_B (GBK * BPAD_B)
#define GSMEM (2 * (ASTG_B + BSTG_B))

template <typename OutT>
__global__ __launch_bounds__(256)
void gemm_f16(const __half* __restrict__ A, const __half* __restrict__ B,
              const float* __restrict__ bias, OutT* __restrict__ C,
              int M, int N, int K)
{
    extern __shared__ __align__(16) char smem[];
    const int tid  = threadIdx.x;
    const int wid  = tid >> 5;
    const int lane = tid & 31;
    const int g = lane >> 2;
    const int t = lane & 3;
    const int wm = (wid >> 2) * 64;
    const int wn = (wid & 3) * 32;
    const int n0 = blockIdx.x * GBN;
    const int m0 = blockIdx.y * GBM;

    const uint32_t smA_u = s2u(smem);
    const uint32_t smB_u = smA_u + 2 * ASTG_B;

    const __half* Ab = A + (size_t)m0 * K;
    const __half* Bb = B + n0;

    float acc[4][4][4];
    #pragma unroll
    for (int i = 0; i < 4; ++i)
        #pragma unroll
        for (int j = 0; j < 4; ++j)
            #pragma unroll
            for (int c = 0; c < 4; ++c) acc[i][j][c] = 0.f;

    const int ntiles = K / GBK;

    #define LOAD_CHUNK(kc, st) do {                                              \
        const int _k0 = (kc) * GBK;                                              \
        const uint32_t _aB = smA_u + (st) * ASTG_B;                              \
        const uint32_t _bB = smB_u + (st) * BSTG_B;                              \
        _Pragma("unroll")                                                        \
        for (int _i = 0; _i < 4; ++_i) {                                         \
            int _idx = tid + _i * 256;                                           \
            int _ar = _idx >> 3, _ac = _idx & 7;                                 \
            cp16(_aB + _ar * APAD_B + _ac * 16,                                  \
                 Ab + (size_t)_ar * K + _k0 + _ac * 8);                          \
            int _br = _idx >> 4, _bc = _idx & 15;                                \
            cp16(_bB + _br * BPAD_B + _bc * 16,                                  \
                 Bb + (size_t)(_k0 + _br) * N + _bc * 8);                        \
        }                                                                        \
        CP_COMMIT();                                                             \
    } while (0)

    LOAD_CHUNK(0, 0);

    for (int kt = 0; kt < ntiles; ++kt) {
        const int s = kt & 1;
        CP_WAIT(0);
        __syncthreads();
        if (kt + 1 < ntiles)
            LOAD_CHUNK(kt + 1, s ^ 1);

        const uint32_t aS = smA_u + s * ASTG_B;
        const uint32_t bS = smB_u + s * BSTG_B;

        #pragma unroll
        for (int ks = 0; ks < 4; ++ks) {
            uint32_t a[4][4], bfr[4][2];
            #pragma unroll
            for (int mf = 0; mf < 4; ++mf) {
                uint32_t addr = aS
                    + (uint32_t)(wm + mf * 16 + (lane & 15)) * APAD_B
                    + (uint32_t)(ks * 16 + ((lane >> 4) << 3)) * 2;
                ldsm_x4(a[mf][0], a[mf][1], a[mf][2], a[mf][3], addr);
            }
            #pragma unroll
            for (int p = 0; p < 2; ++p) {
                uint32_t addr = bS
                    + (uint32_t)(ks * 16 + (lane & 15)) * BPAD_B
                    + (uint32_t)(wn + p * 16 + ((lane >> 4) << 3)) * 2;
                ldsm_x4t(bfr[2 * p][0], bfr[2 * p][1],
                         bfr[2 * p + 1][0], bfr[2 * p + 1][1], addr);
            }
            #pragma unroll
            for (int mf = 0; mf < 4; ++mf)
                #pragma unroll
                for (int nf = 0; nf < 4; ++nf)
                    MMA_F16(acc[mf][nf][0], acc[mf][nf][1],
                            acc[mf][nf][2], acc[mf][nf][3],
                            a[mf][0], a[mf][1], a[mf][2], a[mf][3],
                            bfr[nf][0], bfr[nf][1]);
        }
    }
    #undef LOAD_CHUNK

    #pragma unroll
    for (int mf = 0; mf < 4; ++mf) {
        const int row = m0 + wm + mf * 16 + g;
        #pragma unroll
        for (int nf = 0; nf < 4; ++nf) {
            const int col = n0 + wn + nf * 8 + 2 * t;
            float2 b2 = *reinterpret_cast<const float2*>(bias + col);
            float o00 = acc[mf][nf][0] + b2.x, o01 = acc[mf][nf][1] + b2.y;
            float o10 = acc[mf][nf][2] + b2.x, o11 = acc[mf][nf][3] + b2.y;
            if (sizeof(OutT) == 2) {
                __half* p0 = (__half*)C + (size_t)row * N + col;
                __half* p1 = (__half*)C + (size_t)(row + 8) * N + col;
                *reinterpret_cast<uint32_t*>(p0) = ph2(o00, o01);
                *reinterpret_cast<uint32_t*>(p1) = ph2(o10, o11);
            } else {
                float* p0 = (float*)C + (size_t)row * N + col;
                float* p1 = (float*)C + (size_t)(row + 8) * N + col;
                *reinterpret_cast<float2*>(p0) = make_float2(o00, o01);
                *reinterpret_cast<float2*>(p1) = make_float2(o10, o11);
            }
        }
    }
}

// ---------------------------------------------------------------------------
// Persistent f16 causal flash attention with dynamic LPT scheduling.
// 444 persistent CTAs (128 thr / 4 warps) pull (b,h,qt) items from g_ctr,
// ordered qt-descending (longest first). Per-item body = R15 datapath:
// 64-query tile, 128-key double-buffered smem tiles, x4 ldmatrix.
// ---------------------------------------------------------------------------
#define KSTH 72
#define KROW_B (KSTH * 2)            // 144
#define KTILE_B (128 * KROW_B)       // 18432 per matrix
#define ASTAGE_B (2 * KTILE_B)       // 36864
#define ASMEM (2 * ASTAGE_B)         // 73728  -> 3 CTAs/SM

__global__ __launch_bounds__(128)
void attn_f16(__half* __restrict__ out)
{
    extern __shared__ __align__(16) char asmem[];
    __shared__ int s_idx;
    const int tid  = threadIdx.x;
    const int w    = tid >> 5;
    const int lane = tid & 31;
    const int g = lane >> 2;
    const int t = lane & 3;
    const uint32_t smu = s2u(asmem);

    const int kq_row = lane & 7;
    const int kq_sel = (lane >> 4) & 1;
    const int kq_col = (lane >> 3) & 1;
    const int v_row = lane & 15;
    const int v_sel = (lane >> 4) & 1;

    #define LOAD_TILE(base_, kt_, st_) do {                                       \
        const int _k0 = (kt_) * 128;                                             \
        const uint32_t _kB = smu + (st_) * ASTAGE_B;                             \
        const uint32_t _vB = _kB + KTILE_B;                                      \
        _Pragma("unroll")                                                        \
        for (int _i = 0; _i < 8; ++_i) {                                         \
            int _idx = tid + _i * 128;                                           \
            int _r = _idx >> 3;                                                  \
            int _cb = (_idx & 7) << 4;                                           \
            const __half* _rp = (base_) + (size_t)(_k0 + _r) * row3E + h * HDIM; \
            cp16(_kB + _r * KROW_B + _cb, (const char*)(_rp + EMB) + _cb);       \
            cp16(_vB + _r * KROW_B + _cb, (const char*)(_rp + 2 * EMB) + _cb);   \
        }                                                                        \
        CP_COMMIT();                                                             \
    } while (0)

    const size_t row3E = (size_t)3 * EMB;

    for (;;) {
        if (tid == 0) s_idx = atomicAdd(&g_ctr, 1);
        __syncthreads();               // broadcast + protects smem stage reuse
        const int idx = s_idx;
        if (idx >= NWORK) break;

        // Decode: longest tiles first (qt descending), all (b,h) per qt.
        const int qt = NQT - 1 - (idx >> 6);   // 64 items per qt rank
        const int bh = idx & 63;
        const int b  = bh >> 4;
        const int h  = bh & 15;
        const int q0 = qt * 64;
        const __half* basep = g_qkvh + (size_t)b * SEQ * row3E;

        // Q fragments (pre-scaled by 1/8 — exact in f16)
        uint32_t qa[4][4];
        {
            const __half2 sc = __half2half2(__float2half_rn(0.125f));
            const __half* q0p = basep + (size_t)(q0 + w * 16 + g) * row3E + h * HDIM;
            const __half* q8p = q0p + 8 * row3E;
            #pragma unroll
            for (int ks = 0; ks < 4; ++ks) {
                __half2 v0 = *reinterpret_cast<const __half2*>(q0p + ks * 16 + 2 * t);
                __half2 v1 = *reinterpret_cast<const __half2*>(q8p + ks * 16 + 2 * t);
                __half2 v2 = *reinterpret_cast<const __half2*>(q0p + ks * 16 + 8 + 2 * t);
                __half2 v3 = *reinterpret_cast<const __half2*>(q8p + ks * 16 + 8 + 2 * t);
                v0 = __hmul2(v0, sc); v1 = __hmul2(v1, sc);
                v2 = __hmul2(v2, sc); v3 = __hmul2(v3, sc);
                qa[ks][0] = *reinterpret_cast<uint32_t*>(&v0);
                qa[ks][1] = *reinterpret_cast<uint32_t*>(&v1);
                qa[ks][2] = *reinterpret_cast<uint32_t*>(&v2);
                qa[ks][3] = *reinterpret_cast<uint32_t*>(&v3);
            }
        }

        float m0 = -INFINITY, m1 = -INFINITY, l0 = 0.f, l1 = 0.f;
        float o[8][4];
        #pragma unroll
        for (int nf = 0; nf < 8; ++nf)
            #pragma unroll
            for (int c = 0; c < 4; ++c) o[nf][c] = 0.f;

        const int ntile = (q0 + 64 + 127) / 128;
        LOAD_TILE(basep, 0, 0);

        for (int kt = 0; kt < ntile; ++kt) {
            const int st = kt & 1;
            const int k0 = kt * 128;
            if (kt + 1 < ntile) { CP_WAIT(1); } else { CP_WAIT(0); }
            __syncthreads();
            if (kt + 1 < ntile) LOAD_TILE(basep, kt + 1, st ^ 1);

            const uint32_t kB = smu + st * ASTAGE_B;
            const uint32_t vB = kB + KTILE_B;

            float s[16][4];
            #pragma unroll
            for (int nf = 0; nf < 16; ++nf)
                #pragma unroll
                for (int c = 0; c < 4; ++c) s[nf][c] = 0.f;

            #pragma unroll
            for (int p = 0; p < 8; ++p) {
                uint32_t bf[2][2];
                #pragma unroll
                for (int ks = 0; ks < 4; ++ks) {
                    uint32_t addr = kB
                        + (uint32_t)((2 * p + kq_sel) * 8 + kq_row) * KROW_B
                        + (uint32_t)(ks * 16 + kq_col * 8) * 2;
                    ldsm_x4(bf[0][0], bf[0][1], bf[1][0], bf[1][1], addr);
                    MMA_F16(s[2*p][0], s[2*p][1], s[2*p][2], s[2*p][3],
                            qa[ks][0], qa[ks][1], qa[ks][2], qa[ks][3],
                            bf[0][0], bf[0][1]);
                    MMA_F16(s[2*p+1][0], s[2*p+1][1], s[2*p+1][2], s[2*p+1][3],
                            qa[ks][0], qa[ks][1], qa[ks][2], qa[ks][3],
                            bf[1][0], bf[1][1]);
                }
            }

            if (k0 + 127 > q0 + w * 16) {
                const int r0g = q0 + w * 16 + g;
                #pragma unroll
                for (int nf = 0; nf < 16; ++nf) {
                    const int cg = k0 + nf * 8 + 2 * t;
                    if (cg     > r0g)     s[nf][0] = -INFINITY;
                    if (cg + 1 > r0g)     s[nf][1] = -INFINITY;
                    if (cg     > r0g + 8) s[nf][2] = -INFINITY;
                    if (cg + 1 > r0g + 8) s[nf][3] = -INFINITY;
                }
            }

            float tm0 = -INFINITY, tm1 = -INFINITY;
            #pragma unroll
            for (int nf = 0; nf < 16; ++nf) {
                tm0 = fmaxf(tm0, fmaxf(s[nf][0], s[nf][1]));
                tm1 = fmaxf(tm1, fmaxf(s[nf][2], s[nf][3]));
            }
            tm0 = fmaxf(tm0, __shfl_xor_sync(0xffffffffu, tm0, 1));
            tm0 = fmaxf(tm0, __shfl_xor_sync(0xffffffffu, tm0, 2));
            tm1 = fmaxf(tm1, __shfl_xor_sync(0xffffffffu, tm1, 1));
            tm1 = fmaxf(tm1, __shfl_xor_sync(0xffffffffu, tm1, 2));

            const float m0n = fmaxf(m0, tm0);
            const float m1n = fmaxf(m1, tm1);
            const float c0 = __expf(m0 - m0n);
            const float c1 = __expf(m1 - m1n);
            m0 = m0n; m1 = m1n;

            float ls0 = 0.f, ls1 = 0.f;
            #pragma unroll
            for (int nf = 0; nf < 16; ++nf) {
                s[nf][0] = __expf(s[nf][0] - m0n); ls0 += s[nf][0];
                s[nf][1] = __expf(s[nf][1] - m0n); ls0 += s[nf][1];
                s[nf][2] = __expf(s[nf][2] - m1n); ls1 += s[nf][2];
                s[nf][3] = __expf(s[nf][3] - m1n); ls1 += s[nf][3];
            }
            ls0 += __shfl_xor_sync(0xffffffffu, ls0, 1);
            ls0 += __shfl_xor_sync(0xffffffffu, ls0, 2);
            ls1 += __shfl_xor_sync(0xffffffffu, ls1, 1);
            ls1 += __shfl_xor_sync(0xffffffffu, ls1, 2);
            l0 = l0 * c0 + ls0;
            l1 = l1 * c1 + ls1;

            #pragma unroll
            for (int nf = 0; nf < 8; ++nf) {
                o[nf][0] *= c0; o[nf][1] *= c0;
                o[nf][2] *= c1; o[nf][3] *= c1;
            }

            uint32_t pa[8][4];
            #pragma unroll
            for (int ks = 0; ks < 8; ++ks) {
                pa[ks][0] = ph2(s[2 * ks][0],     s[2 * ks][1]);
                pa[ks][1] = ph2(s[2 * ks][2],     s[2 * ks][3]);
                pa[ks][2] = ph2(s[2 * ks + 1][0], s[2 * ks + 1][1]);
                pa[ks][3] = ph2(s[2 * ks + 1][2], s[2 * ks + 1][3]);
            }

            #pragma unroll
            for (int p = 0; p < 4; ++p) {
                #pragma unroll
                for (int ks = 0; ks < 8; ++ks) {
                    uint32_t v0, v1, v2, v3;
                    uint32_t addr = vB
                        + (uint32_t)(ks * 16 + v_row) * KROW_B
                        + (uint32_t)((2 * p + v_sel) * 8) * 2;
                    ldsm_x4t(v0, v1, v2, v3, addr);
                    MMA_F16(o[2*p][0], o[2*p][1], o[2*p][2], o[2*p][3],
                            pa[ks][0], pa[ks][1], pa[ks][2], pa[ks][3], v0, v1);
                    MMA_F16(o[2*p+1][0], o[2*p+1][1], o[2*p+1][2], o[2*p+1][3],
                            pa[ks][0], pa[ks][1], pa[ks][2], pa[ks][3], v2, v3);
                }
            }
        }

        // Epilogue -> f16
        const float inv0 = 1.f / l0;
        const float inv1 = 1.f / l1;
        const int gr0 = q0 + w * 16 + g;
        __half* op0 = out + ((size_t)b * SEQ + gr0) * EMB + h * HDIM;
        __half* op1 = op0 + 8 * EMB;
        #pragma unroll
        for (int nf = 0; nf < 8; ++nf) {
            const int col = nf * 8 + 2 * t;
            *reinterpret_cast<uint32_t*>(op0 + col) =
                ph2(o[nf][0] * inv0, o[nf][1] * inv0);
            *reinterpret_cast<uint32_t*>(op1 + col) =
                ph2(o[nf][2] * inv1, o[nf][3] * inv1);
        }
    }
    #undef LOAD_TILE
}

// ---------------------------------------------------------------------------
// Launch
// ---------------------------------------------------------------------------
extern "C" void kernel_launch(void* const* d_in, const int* in_sizes, int n_in,
                              void* d_out, int out_size)
{
    (void)in_sizes; (void)n_in; (void)out_size;
    const float* x     = (const float*)d_in[0];
    const float* W_qkv = (const float*)d_in[1];
    const float* b_qkv = (const float*)d_in[2];
    const float* W_o   = (const float*)d_in[3];
    const float* b_o   = (const float*)d_in[4];
    float* out = (float*)d_out;

    __half *xh = nullptr, *wqkvh = nullptr, *woh = nullptr;
    __half *qkvh = nullptr, *attnh = nullptr;
    cudaGetSymbolAddress((void**)&xh,    g_xh);
    cudaGetSymbolAddress((void**)&wqkvh, g_wqkvh);
    cudaGetSymbolAddress((void**)&woh,   g_woh);
    cudaGetSymbolAddress((void**)&qkvh,  g_qkvh);
    cudaGetSymbolAddress((void**)&attnh, g_attnh);

    cudaFuncSetAttribute(gemm_f16<__half>,
                         cudaFuncAttributeMaxDynamicSharedMemorySize, GSMEM);
    cudaFuncSetAttribute(gemm_f16<float>,
                         cudaFuncAttributeMaxDynamicSharedMemorySize, GSMEM);
    cudaFuncSetAttribute(attn_f16,
                         cudaFuncAttributeMaxDynamicSharedMemorySize, ASMEM);

    // 0) fused pre-pass (x, W_qkv, W_o -> f16; resets work counter)
    prepass_cvt<<<(N4_ALL + 255) / 256, 256>>>(x, W_qkv, W_o);

    // 1) QKV projection (f16 out)
    gemm_f16<__half><<<dim3(3 * EMB / GBN, M_ROWS / GBM), 256, GSMEM>>>(
        xh, wqkvh, b_qkv, qkvh, M_ROWS, 3 * EMB, EMB);

    // 2) persistent causal flash attention (dynamic LPT scheduling)
    attn_f16<<<NPERS, 128, ASMEM>>>(attnh);

    // 3) Output projection (f32 out)
    gemm_f16<float><<<dim3(EMB / GBN, M_ROWS / GBM), 256, GSMEM>>>(
        attnh, woh, b_o, out, M_ROWS, EMB, EMB);
}